// round 11
// baseline (speedup 1.0000x reference)
#include <cuda_runtime.h>
#include <cuda_bf16.h>
#include <cstdint>

#define BATCH 8
#define C 512
#define N 8192
#define HEADS 8
#define DIM_HEAD 32
#define HID 256
#define QKV_ROWS 768
#define KV_ROWS 512
#define SCALE 0.17677669529663687f
#define EPS 1e-5f
#define NSEG 16
#define CSEG (N / NSEG)

// ---------------- scratch (device globals; allocation-free rule) ------------
__device__ __align__(256) __nv_bfloat16 g_kv[(size_t)BATCH * KV_ROWS * N];   // 64 MB
__device__ __align__(256) __nv_bfloat16 g_xT[(size_t)BATCH * N * C];         // 64 MB
__device__ __align__(256) __nv_bfloat16 g_wqkv_bf[QKV_ROWS * C];
__device__ __align__(256) __nv_bfloat16 g_wqT[C * HID];                      // wq_g transposed [c][r]
__device__ __align__(256) __nv_bfloat16 g_wfold[(size_t)BATCH * C * HID];    // W' = w_out·ctx (2 MB)
__device__ __align__(256) __nv_bfloat16 g_wfold2[(size_t)BATCH * C * C];     // M = SCALE·W'·wq_g (4 MB)
__device__ __align__(256) float g_psum[8][BATCH * N];
__device__ __align__(256) float g_psumsq[8][BATCH * N];
__device__ __align__(256) float g_mu[BATCH * N];
__device__ __align__(256) float g_rstd[BATCH * N];
__device__ __align__(256) float g_Aw[QKV_ROWS];
__device__ __align__(256) float g_Bw[QKV_ROWS];
__device__ __align__(256) float g_A2[BATCH * C];
__device__ __align__(256) float g_B2[BATCH * C];
__device__ __align__(256) float g_ctxp[(size_t)NSEG * BATCH * HEADS * 1024];

// ---------------- PTX helpers (generic-target safe: sm_80+) -----------------
__device__ __forceinline__ uint32_t smem_u32(const void* p) {
    uint32_t a;
    asm("{ .reg .u64 t; cvta.to.shared.u64 t, %1; cvt.u32.u64 %0, t; }"
        : "=r"(a) : "l"(p));
    return a;
}

__device__ __forceinline__ void cp_async16(uint32_t s, const void* g) {
    asm volatile("cp.async.cg.shared.global [%0], [%1], 16;" :: "r"(s), "l"(g));
}
#define CP_COMMIT asm volatile("cp.async.commit_group;")
#define CP_WAIT3 asm volatile("cp.async.wait_group 3;")
#define CP_WAIT2 asm volatile("cp.async.wait_group 2;")

__device__ __forceinline__ void ldsm4(uint32_t* r, uint32_t addr) {
    asm volatile("ldmatrix.sync.aligned.m8n8.x4.shared.b16 {%0,%1,%2,%3}, [%4];"
                 : "=r"(r[0]), "=r"(r[1]), "=r"(r[2]), "=r"(r[3]) : "r"(addr));
}

__device__ __forceinline__ void mma16816(float* d, const uint32_t* a,
                                         uint32_t b0, uint32_t b1) {
    asm volatile(
        "mma.sync.aligned.m16n8k16.row.col.f32.bf16.bf16.f32 "
        "{%0,%1,%2,%3}, {%4,%5,%6,%7}, {%8,%9}, {%0,%1,%2,%3};"
        : "+f"(d[0]), "+f"(d[1]), "+f"(d[2]), "+f"(d[3])
        : "r"(a[0]), "r"(a[1]), "r"(a[2]), "r"(a[3]), "r"(b0), "r"(b1));
}

#define SPAD 40         // smem row stride (bf16): 80B, conflict-free ldsm
#define STG_E 5120      // per-stage elems: 128*SPAD
#define QSTAGES 5       // deep pipeline (K=512 GEMMs)
#define FSTAGES 4       // shallow pipeline (K=256 GEMM)
#define DSM5_B ((2 * QSTAGES * STG_E) * 2)   // 102400 B
#define DSM4_B ((2 * FSTAGES * STG_E) * 2)   // 81920 B
#define TST 136         // epilogue staging stride

// ---------------------------------------------------------------------------
// 1) fold g into w_qkv -> bf16; A[o]=sum(bf16 wg), B[o]=sum(w*b_ln)
// ---------------------------------------------------------------------------
__global__ __launch_bounds__(256) void prep_w(const float* __restrict__ w,
                                              const float* __restrict__ g,
                                              const float* __restrict__ bln) {
    int o = blockIdx.x;
    int t = threadIdx.x;
    float a = 0.f, bb = 0.f;
    for (int c = t; c < C; c += 256) {
        float wv = w[o * C + c];
        __nv_bfloat16 hb = __float2bfloat16(wv * g[c]);
        g_wqkv_bf[o * C + c] = hb;
        a += __bfloat162float(hb);
        bb += wv * bln[c];
    }
    __shared__ float sa[8], sb[8];
    for (int off = 16; off; off >>= 1) {
        a += __shfl_xor_sync(~0u, a, off);
        bb += __shfl_xor_sync(~0u, bb, off);
    }
    if ((t & 31) == 0) { sa[t >> 5] = a; sb[t >> 5] = bb; }
    __syncthreads();
    if (t == 0) {
        float A = 0.f, Bv = 0.f;
        for (int i = 0; i < 8; i++) { A += sa[i]; Bv += sb[i]; }
        g_Aw[o] = A;
        g_Bw[o] = Bv;
    }
}

// transpose q weight rows: g_wqT[c][r] = wq_g[r][c], r in [0,HID)
__global__ __launch_bounds__(256) void wq_transpose() {
    int c = blockIdx.x;
    int r = threadIdx.x;
    g_wqT[c * HID + r] = g_wqkv_bf[r * C + c];
}

// ---------------------------------------------------------------------------
// 2) transpose+convert x -> xT bf16 [b][j][c]  + LN partial sums (fused)
// ---------------------------------------------------------------------------
__global__ __launch_bounds__(256) void transpose_x(const float* __restrict__ x) {
    __shared__ float ts[64][65];
    __shared__ float red[4][64], red2[4][64];
    int b = blockIdx.z, cb = blockIdx.y, j0 = blockIdx.x * 64;
    int c0 = cb * 64;
    int tid = threadIdx.x;
    const float* xb = x + ((size_t)b * C + c0) * N + j0;
#pragma unroll
    for (int it = 0; it < 16; it++) {
        int idx = tid + it * 256;
        int r = idx >> 6, cl = idx & 63;
        ts[r][cl] = xb[(size_t)r * N + cl];
    }
    __syncthreads();
    {
        int p = tid >> 6, jc = tid & 63;
        float s = 0.f, sq = 0.f;
#pragma unroll
        for (int r = 0; r < 16; r++) {
            float v = ts[p * 16 + r][jc];
            s += v;
            sq += v * v;
        }
        red[p][jc] = s;
        red2[p][jc] = sq;
    }
    __syncthreads();
    if (tid < 64) {
        int jc = tid;
        float S = red[0][jc] + red[1][jc] + red[2][jc] + red[3][jc];
        float SQ = red2[0][jc] + red2[1][jc] + red2[2][jc] + red2[3][jc];
        g_psum[cb][b * N + j0 + jc] = S;
        g_psumsq[cb][b * N + j0 + jc] = SQ;
    }
    __nv_bfloat16* ob = g_xT + ((size_t)b * N + j0) * C + c0;
#pragma unroll
    for (int it = 0; it < 2; it++) {
        int u = tid + it * 256;
        int jr = u >> 3, c8 = (u & 7) * 8;
        __nv_bfloat162 tmp[4];
#pragma unroll
        for (int q = 0; q < 4; q++)
            tmp[q] = __floats2bfloat162_rn(ts[c8 + 2 * q][jr], ts[c8 + 2 * q + 1][jr]);
        *(uint4*)(ob + (size_t)jr * C + c8) = *(uint4*)tmp;
    }
}

__global__ __launch_bounds__(256) void ln_finalize() {
    int j = blockIdx.x * 256 + threadIdx.x;
    float s = 0.f, sq = 0.f;
#pragma unroll
    for (int cb = 0; cb < 8; cb++) {
        s += g_psum[cb][j];
        sq += g_psumsq[cb][j];
    }
    float mu = s * (1.0f / C);
    float var = sq * (1.0f / C) - mu * mu;
    g_mu[j] = mu;
    g_rstd[j] = rsqrtf(var + EPS);
}

// ---------------------------------------------------------------------------
// 3) KV GEMM (k,v rows only): CTA 128x128, warp 64x32, 2 CTA/SM, 5 stages
// ---------------------------------------------------------------------------
__global__ void __launch_bounds__(256, 2) qkv_mma() {
    extern __shared__ __nv_bfloat16 dsm[];
    __nv_bfloat16* Asm = dsm;
    __nv_bfloat16* Bsm = dsm + QSTAGES * STG_E;
    int tid = threadIdx.x, wid = tid >> 5, lane = tid & 31;
    int wm = wid >> 2, wn = wid & 3;
    int b = blockIdx.z, o0 = blockIdx.y * 128, j0 = blockIdx.x * 128;
    const __nv_bfloat16* Ag = g_wqkv_bf + (size_t)(HID + o0) * C;
    const __nv_bfloat16* Bg = g_xT + ((size_t)b * N + j0) * C;
    int lrow = tid >> 2, lseg = (tid & 3) * 8;

    float d[4][4][4] = {};
    const int L = C / 32;   // 16

#pragma unroll
    for (int s = 0; s < QSTAGES - 1; s++) {
        int k0 = s * 32;
        cp_async16(smem_u32(Asm + s * STG_E + lrow * SPAD + lseg), Ag + (size_t)lrow * C + k0 + lseg);
        cp_async16(smem_u32(Asm + s * STG_E + (lrow + 64) * SPAD + lseg), Ag + (size_t)(lrow + 64) * C + k0 + lseg);
        cp_async16(smem_u32(Bsm + s * STG_E + lrow * SPAD + lseg), Bg + (size_t)lrow * C + k0 + lseg);
        cp_async16(smem_u32(Bsm + s * STG_E + (lrow + 64) * SPAD + lseg), Bg + (size_t)(lrow + 64) * C + k0 + lseg);
        CP_COMMIT;
    }

    int r = lane & 15;
    uint32_t aB = smem_u32(Asm) + (uint32_t)((wm * 64 + r) * SPAD) * 2 + (lane & 16);
    uint32_t bB = smem_u32(Bsm) + (uint32_t)((wn * 32 + r) * SPAD) * 2 + (lane & 16);

    for (int i = 0; i < L; i++) {
        CP_WAIT3;
        __syncthreads();
        int pf = i + QSTAGES - 1;
        if (pf < L) {
            int k0 = pf * 32;
            int st = pf % QSTAGES;
            cp_async16(smem_u32(Asm + st * STG_E + lrow * SPAD + lseg), Ag + (size_t)lrow * C + k0 + lseg);
            cp_async16(smem_u32(Asm + st * STG_E + (lrow + 64) * SPAD + lseg), Ag + (size_t)(lrow + 64) * C + k0 + lseg);
            cp_async16(smem_u32(Bsm + st * STG_E + lrow * SPAD + lseg), Bg + (size_t)lrow * C + k0 + lseg);
            cp_async16(smem_u32(Bsm + st * STG_E + (lrow + 64) * SPAD + lseg), Bg + (size_t)(lrow + 64) * C + k0 + lseg);
        }
        CP_COMMIT;
        int st = i % QSTAGES;
        uint32_t aS = aB + st * (STG_E * 2);
        uint32_t bS = bB + st * (STG_E * 2);
#pragma unroll
        for (int s = 0; s < 2; s++) {
            uint32_t a[4][4], bb[2][4];
#pragma unroll
            for (int mt = 0; mt < 4; mt++)
                ldsm4(a[mt], aS + mt * (16 * SPAD * 2) + s * 32);
#pragma unroll
            for (int ng = 0; ng < 2; ng++)
                ldsm4(bb[ng], bS + ng * (16 * SPAD * 2) + s * 32);
#pragma unroll
            for (int mt = 0; mt < 4; mt++)
#pragma unroll
                for (int nt = 0; nt < 4; nt++)
                    mma16816(d[mt][nt], a[mt], bb[nt >> 1][nt & 1], bb[nt >> 1][2 + (nt & 1)]);
        }
    }
    __syncthreads();

    // epilogue: folded-LN affine -> staged coalesced bf16 store to g_kv
    int g = lane >> 2, qq = lane & 3;
    const float* mup = g_mu + (size_t)b * N + j0;
    const float* rp = g_rstd + (size_t)b * N + j0;
    __nv_bfloat16* T = dsm;
#pragma unroll
    for (int mt = 0; mt < 4; mt++) {
        int lr = wm * 64 + mt * 16 + g;
        int o_r = HID + o0 + lr;
        float A0 = g_Aw[o_r], B0 = g_Bw[o_r];
        float A1 = g_Aw[o_r + 8], B1 = g_Bw[o_r + 8];
#pragma unroll
        for (int nt = 0; nt < 4; nt++) {
            int jc = wn * 32 + nt * 8 + qq * 2;
            float m0 = mup[jc], m1 = mup[jc + 1];
            float r0 = rp[jc], r1 = rp[jc + 1];
            float v00 = (d[mt][nt][0] - m0 * A0) * r0 + B0;
            float v01 = (d[mt][nt][1] - m1 * A0) * r1 + B0;
            float v10 = (d[mt][nt][2] - m0 * A1) * r0 + B1;
            float v11 = (d[mt][nt][3] - m1 * A1) * r1 + B1;
            *(__nv_bfloat162*)(T + lr * TST + jc) = __floats2bfloat162_rn(v00, v01);
            *(__nv_bfloat162*)(T + (lr + 8) * TST + jc) = __floats2bfloat162_rn(v10, v11);
        }
    }
    __syncthreads();
    __nv_bfloat16* outb = g_kv + (size_t)b * KV_ROWS * N + (size_t)o0 * N + j0;
#pragma unroll
    for (int it = 0; it < 8; it++) {
        int row = it * 16 + (tid >> 4);
        int cc = (tid & 15) * 8;
        *(uint4*)(outb + (size_t)row * N + cc) = *(uint4*)(T + row * TST + cc);
    }
}

// ---------------------------------------------------------------------------
// 4) softmax over sequence for each k row (rows 0-255 of g_kv, in place)
// ---------------------------------------------------------------------------
__global__ __launch_bounds__(256) void softmax_k() {
    int row = blockIdx.x;
    int b = row >> 8;
    int cc = row & 255;
    __nv_bfloat162* p2 = (__nv_bfloat162*)(g_kv + ((size_t)b * KV_ROWS + cc) * N);
    int t = threadIdx.x;
    float2 v[16];
    float mx = -1e30f;
#pragma unroll
    for (int i = 0; i < 16; i++) {
        v[i] = __bfloat1622float2(p2[t + i * 256]);
        mx = fmaxf(mx, fmaxf(v[i].x, v[i].y));
    }
    __shared__ float sm[8], ss[8];
    for (int off = 16; off; off >>= 1) mx = fmaxf(mx, __shfl_xor_sync(~0u, mx, off));
    if ((t & 31) == 0) sm[t >> 5] = mx;
    __syncthreads();
    mx = sm[0];
#pragma unroll
    for (int w = 1; w < 8; w++) mx = fmaxf(mx, sm[w]);
    float s = 0.f;
#pragma unroll
    for (int i = 0; i < 16; i++) {
        v[i].x = __expf(v[i].x - mx);
        v[i].y = __expf(v[i].y - mx);
        s += v[i].x + v[i].y;
    }
    for (int off = 16; off; off >>= 1) s += __shfl_xor_sync(~0u, s, off);
    if ((t & 31) == 0) ss[t >> 5] = s;
    __syncthreads();
    s = 0.f;
#pragma unroll
    for (int w = 0; w < 8; w++) s += ss[w];
    float inv = 1.0f / s;
#pragma unroll
    for (int i = 0; i < 16; i++)
        p2[t + i * 256] = __floats2bfloat162_rn(v[i].x * inv, v[i].y * inv);
}

// ---------------------------------------------------------------------------
// 5) context partials (bf16 in, fp32 out) — conflict-free smem (pad 129)
// ---------------------------------------------------------------------------
__global__ __launch_bounds__(256) void ctx_partial() {
    int s = blockIdx.x;
    int bh = blockIdx.y;
    int b = bh >> 3, h = bh & 7;
    const __nv_bfloat16* kb = g_kv + ((size_t)b * KV_ROWS + h * 32) * N;
    const __nv_bfloat16* vb = g_kv + ((size_t)b * KV_ROWS + 256 + h * 32) * N;
    __shared__ float ks[32][129];
    __shared__ float vs[32][129];
    int tid = threadIdx.x;
    int d0 = (tid >> 4) * 2;
    int e0 = (tid & 15) * 2;
    float a00 = 0.f, a01 = 0.f, a10 = 0.f, a11 = 0.f;
    for (int j0 = s * CSEG; j0 < (s + 1) * CSEG; j0 += 128) {
#pragma unroll
        for (int it = 0; it < 2; it++) {
            int u = tid + it * 256;
            int row = u >> 4, c8 = (u & 15) * 8;
            uint4 kv = *(const uint4*)(kb + (size_t)row * N + j0 + c8);
            uint4 vv = *(const uint4*)(vb + (size_t)row * N + j0 + c8);
            __nv_bfloat162* hk = (__nv_bfloat162*)&kv;
            __nv_bfloat162* hv = (__nv_bfloat162*)&vv;
#pragma unroll
            for (int q = 0; q < 4; q++) {
                float2 fk = __bfloat1622float2(hk[q]);
                float2 fv = __bfloat1622float2(hv[q]);
                ks[row][c8 + 2 * q] = fk.x;
                ks[row][c8 + 2 * q + 1] = fk.y;
                vs[row][c8 + 2 * q] = fv.x;
                vs[row][c8 + 2 * q + 1] = fv.y;
            }
        }
        __syncthreads();
#pragma unroll 8
        for (int jj = 0; jj < 128; jj++) {
            float k0v = ks[d0][jj], k1v = ks[d0 + 1][jj];
            float v0v = vs[e0][jj], v1v = vs[e0 + 1][jj];
            a00 += k0v * v0v;
            a01 += k0v * v1v;
            a10 += k1v * v0v;
            a11 += k1v * v1v;
        }
        __syncthreads();
    }
    float* outp = g_ctxp + ((size_t)s * 64 + bh) * 1024;
    outp[d0 * 32 + e0] = a00;
    outp[d0 * 32 + e0 + 1] = a01;
    outp[(d0 + 1) * 32 + e0] = a10;
    outp[(d0 + 1) * 32 + e0 + 1] = a11;
}

// ---------------------------------------------------------------------------
// 6) fold context into output weights (array-free): W'[b][o][h*32+d]
// ---------------------------------------------------------------------------
__global__ __launch_bounds__(256) void fold_w(const float* __restrict__ wout) {
    int h = blockIdx.x, b = blockIdx.y;
    int bh = b * 8 + h;
    int tid = threadIdx.x;
    __shared__ float ctx[32][33];
    for (int i = tid; i < 1024; i += 256) {
        float s = 0.f;
#pragma unroll
        for (int sg = 0; sg < NSEG; sg++) s += g_ctxp[((size_t)sg * 64 + bh) * 1024 + i];
        ctx[i >> 5][i & 31] = s;
    }
    __syncthreads();
    int dd = tid & 31;
    for (int o = tid >> 5; o < C; o += 8) {
        const float* wrow = wout + (size_t)o * HID + h * 32;
        float s = 0.f;
#pragma unroll
        for (int e = 0; e < 32; e++) s += wrow[e] * ctx[dd][e];
        g_wfold[((size_t)b * C + o) * HID + h * 32 + dd] = __float2bfloat16(s);
    }
}

// ---------------------------------------------------------------------------
// 7) fold_w2: M[b][o][c] = SCALE * sum_r W'[b][o][r] * wq_g[r][c]
//    GEMM 512x512xK=256 per batch (A=W', B=g_wqT), bf16 out.
// ---------------------------------------------------------------------------
__global__ void __launch_bounds__(256, 2) fold_w2() {
    extern __shared__ __nv_bfloat16 dsm[];
    __nv_bfloat16* Asm = dsm;
    __nv_bfloat16* Bsm = dsm + FSTAGES * STG_E;
    int tid = threadIdx.x, wid = tid >> 5, lane = tid & 31;
    int wm = wid >> 2, wn = wid & 3;
    int b = blockIdx.z, o0 = blockIdx.y * 128, c0 = blockIdx.x * 128;
    const __nv_bfloat16* Ag = g_wfold + (size_t)b * C * HID + (size_t)o0 * HID;
    const __nv_bfloat16* Bg = g_wqT + (size_t)c0 * HID;
    int lrow = tid >> 2, lseg = (tid & 3) * 8;

    float d[4][4][4] = {};
    const int L = HID / 32;   // 8

#pragma unroll
    for (int s = 0; s < FSTAGES - 1; s++) {
        int k0 = s * 32;
        cp_async16(smem_u32(Asm + s * STG_E + lrow * SPAD + lseg), Ag + (size_t)lrow * HID + k0 + lseg);
        cp_async16(smem_u32(Asm + s * STG_E + (lrow + 64) * SPAD + lseg), Ag + (size_t)(lrow + 64) * HID + k0 + lseg);
        cp_async16(smem_u32(Bsm + s * STG_E + lrow * SPAD + lseg), Bg + (size_t)lrow * HID + k0 + lseg);
        cp_async16(smem_u32(Bsm + s * STG_E + (lrow + 64) * SPAD + lseg), Bg + (size_t)(lrow + 64) * HID + k0 + lseg);
        CP_COMMIT;
    }

    int r = lane & 15;
    uint32_t aB = smem_u32(Asm) + (uint32_t)((wm * 64 + r) * SPAD) * 2 + (lane & 16);
    uint32_t bB = smem_u32(Bsm) + (uint32_t)((wn * 32 + r) * SPAD) * 2 + (lane & 16);

    for (int i = 0; i < L; i++) {
        CP_WAIT2;
        __syncthreads();
        int pf = i + FSTAGES - 1;
        if (pf < L) {
            int k0 = pf * 32, st = pf & (FSTAGES - 1);
            cp_async16(smem_u32(Asm + st * STG_E + lrow * SPAD + lseg), Ag + (size_t)lrow * HID + k0 + lseg);
            cp_async16(smem_u32(Asm + st * STG_E + (lrow + 64) * SPAD + lseg), Ag + (size_t)(lrow + 64) * HID + k0 + lseg);
            cp_async16(smem_u32(Bsm + st * STG_E + lrow * SPAD + lseg), Bg + (size_t)lrow * HID + k0 + lseg);
            cp_async16(smem_u32(Bsm + st * STG_E + (lrow + 64) * SPAD + lseg), Bg + (size_t)(lrow + 64) * HID + k0 + lseg);
        }
        CP_COMMIT;
        int st = i & (FSTAGES - 1);
        uint32_t aS = aB + st * (STG_E * 2);
        uint32_t bS = bB + st * (STG_E * 2);
#pragma unroll
        for (int s = 0; s < 2; s++) {
            uint32_t a[4][4], bb[2][4];
#pragma unroll
            for (int mt = 0; mt < 4; mt++)
                ldsm4(a[mt], aS + mt * (16 * SPAD * 2) + s * 32);
#pragma unroll
            for (int ng = 0; ng < 2; ng++)
                ldsm4(bb[ng], bS + ng * (16 * SPAD * 2) + s * 32);
#pragma unroll
            for (int mt = 0; mt < 4; mt++)
#pragma unroll
                for (int nt = 0; nt < 4; nt++)
                    mma16816(d[mt][nt], a[mt], bb[nt >> 1][nt & 1], bb[nt >> 1][2 + (nt & 1)]);
        }
    }

    int g = lane >> 2, qq = lane & 3;
    __nv_bfloat16* ob = g_wfold2 + ((size_t)b * C + o0) * C + c0;
#pragma unroll
    for (int mt = 0; mt < 4; mt++) {
        int lr = wm * 64 + mt * 16 + g;
#pragma unroll
        for (int nt = 0; nt < 4; nt++) {
            int jc = wn * 32 + nt * 8 + qq * 2;
            *(__nv_bfloat162*)(ob + (size_t)lr * C + jc) =
                __floats2bfloat162_rn(d[mt][nt][0] * SCALE, d[mt][nt][1] * SCALE);
            *(__nv_bfloat162*)(ob + (size_t)(lr + 8) * C + jc) =
                __floats2bfloat162_rn(d[mt][nt][2] * SCALE, d[mt][nt][3] * SCALE);
        }
    }
}

// ---------------------------------------------------------------------------
// 8) A2[b][o] = SCALE*sum_r W'[o][r]*A[r];  B2 likewise with B[r]
// ---------------------------------------------------------------------------
__global__ __launch_bounds__(256) void a2b2() {
    int b = blockIdx.y;
    int o = blockIdx.x * 8 + (threadIdx.x >> 5);
    int lane = threadIdx.x & 31;
    const __nv_bfloat16* wp = g_wfold + ((size_t)b * C + o) * HID;
    float a = 0.f, bb = 0.f;
#pragma unroll
    for (int r = lane; r < HID; r += 32) {
        float w = __bfloat162float(wp[r]);
        a += w * g_Aw[r];
        bb += w * g_Bw[r];
    }
    for (int off = 16; off; off >>= 1) {
        a += __shfl_xor_sync(~0u, a, off);
        bb += __shfl_xor_sync(~0u, bb, off);
    }
    if (lane == 0) {
        g_A2[b * C + o] = a * SCALE;
        g_B2[b * C + o] = bb * SCALE;
    }
}

// ---------------------------------------------------------------------------
// 9) final GEMM: out = LN-affine(M[b] . xT) + b_out + x   (K=512, 5 stages)
// ---------------------------------------------------------------------------
__global__ void __launch_bounds__(256, 2) final_mma(const float* __restrict__ bout,
                                                    const float* __restrict__ x,
                                                    float* __restrict__ out) {
    extern __shared__ __nv_bfloat16 dsm[];
    __nv_bfloat16* Asm = dsm;
    __nv_bfloat16* Bsm = dsm + QSTAGES * STG_E;
    int tid = threadIdx.x, wid = tid >> 5, lane = tid & 31;
    int wm = wid >> 2, wn = wid & 3;
    int b = blockIdx.z, o0 = blockIdx.y * 128, j0 = blockIdx.x * 128;
    const __nv_bfloat16* Ag = g_wfold2 + ((size_t)b * C + o0) * C;
    const __nv_bfloat16* Bg = g_xT + ((size_t)b * N + j0) * C;
    int lrow = tid >> 2, lseg = (tid & 3) * 8;

    float d[4][4][4] = {};
    const int L = C / 32;   // 16

#pragma unroll
    for (int s = 0; s < QSTAGES - 1; s++) {
        int k0 = s * 32;
        cp_async16(smem_u32(Asm + s * STG_E + lrow * SPAD + lseg), Ag + (size_t)lrow * C + k0 + lseg);
        cp_async16(smem_u32(Asm + s * STG_E + (lrow + 64) * SPAD + lseg), Ag + (size_t)(lrow + 64) * C + k0 + lseg);
        cp_async16(smem_u32(Bsm + s * STG_E + lrow * SPAD + lseg), Bg + (size_t)lrow * C + k0 + lseg);
        cp_async16(smem_u32(Bsm + s * STG_E + (lrow + 64) * SPAD + lseg), Bg + (size_t)(lrow + 64) * C + k0 + lseg);
        CP_COMMIT;
    }

    int r = lane & 15;
    uint32_t aB = smem_u32(Asm) + (uint32_t)((wm * 64 + r) * SPAD) * 2 + (lane & 16);
    uint32_t bB = smem_u32(Bsm) + (uint32_t)((wn * 32 + r) * SPAD) * 2 + (lane & 16);

    for (int i = 0; i < L; i++) {
        CP_WAIT3;
        __syncthreads();
        int pf = i + QSTAGES - 1;
        if (pf < L) {
            int k0 = pf * 32;
            int st = pf % QSTAGES;
            cp_async16(smem_u32(Asm + st * STG_E + lrow * SPAD + lseg), Ag + (size_t)lrow * C + k0 + lseg);
            cp_async16(smem_u32(Asm + st * STG_E + (lrow + 64) * SPAD + lseg), Ag + (size_t)(lrow + 64) * C + k0 + lseg);
            cp_async16(smem_u32(Bsm + st * STG_E + lrow * SPAD + lseg), Bg + (size_t)lrow * C + k0 + lseg);
            cp_async16(smem_u32(Bsm + st * STG_E + (lrow + 64) * SPAD + lseg), Bg + (size_t)(lrow + 64) * C + k0 + lseg);
        }
        CP_COMMIT;
        int st = i % QSTAGES;
        uint32_t aS = aB + st * (STG_E * 2);
        uint32_t bS = bB + st * (STG_E * 2);
#pragma unroll
        for (int s = 0; s < 2; s++) {
            uint32_t a[4][4], bb[2][4];
#pragma unroll
            for (int mt = 0; mt < 4; mt++)
                ldsm4(a[mt], aS + mt * (16 * SPAD * 2) + s * 32);
#pragma unroll
            for (int ng = 0; ng < 2; ng++)
                ldsm4(bb[ng], bS + ng * (16 * SPAD * 2) + s * 32);
#pragma unroll
            for (int mt = 0; mt < 4; mt++)
#pragma unroll
                for (int nt = 0; nt < 4; nt++)
                    mma16816(d[mt][nt], a[mt], bb[nt >> 1][nt & 1], bb[nt >> 1][2 + (nt & 1)]);
        }
    }

    int g = lane >> 2, qq = lane & 3;
    const float* mup = g_mu + (size_t)b * N + j0;
    const float* rp = g_rstd + (size_t)b * N + j0;
    const float* xb = x + (size_t)b * C * N + j0;
    float* ob = out + (size_t)b * C * N + j0;
#pragma unroll
    for (int mt = 0; mt < 4; mt++) {
        int o_r = o0 + wm * 64 + mt * 16 + g;
        float A20 = g_A2[b * C + o_r], B20 = g_B2[b * C + o_r];
        float A21 = g_A2[b * C + o_r + 8], B21 = g_B2[b * C + o_r + 8];
        float bo0 = bout[o_r], bo1 = bout[o_r + 8];
#pragma unroll
        for (int nt = 0; nt < 4; nt++) {
            int jc = wn * 32 + nt * 8 + qq * 2;
            float m0 = mup[jc], m1 = mup[jc + 1];
            float r0 = rp[jc], r1 = rp[jc + 1];
            float2 x0 = *(const float2*)(xb + (size_t)o_r * N + jc);
            float2 x1 = *(const float2*)(xb + (size_t)(o_r + 8) * N + jc);
            float2 v0, v1;
            v0.x = (d[mt][nt][0] - m0 * A20) * r0 + B20 + bo0 + x0.x;
            v0.y = (d[mt][nt][1] - m1 * A20) * r1 + B20 + bo0 + x0.y;
            v1.x = (d[mt][nt][2] - m0 * A21) * r0 + B21 + bo1 + x1.x;
            v1.y = (d[mt][nt][3] - m1 * A21) * r1 + B21 + bo1 + x1.y;
            *(float2*)(ob + (size_t)o_r * N + jc) = v0;
            *(float2*)(ob + (size_t)(o_r + 8) * N + jc) = v1;
        }
    }
}

// ---------------------------------------------------------------------------
extern "C" void kernel_launch(void* const* d_in, const int* in_sizes, int n_in,
                              void* d_out, int out_size) {
    const float* x = (const float*)d_in[0];
    const float* g = (const float*)d_in[1];
    const float* bln = (const float*)d_in[2];
    const float* wqkv = (const float*)d_in[3];
    const float* wout = (const float*)d_in[4];
    const float* bout = (const float*)d_in[5];
    float* out = (float*)d_out;

    cudaFuncSetAttribute(qkv_mma, cudaFuncAttributeMaxDynamicSharedMemorySize, DSM5_B);
    cudaFuncSetAttribute(final_mma, cudaFuncAttributeMaxDynamicSharedMemorySize, DSM5_B);
    cudaFuncSetAttribute(fold_w2, cudaFuncAttributeMaxDynamicSharedMemorySize, DSM4_B);

    prep_w<<<QKV_ROWS, 256>>>(wqkv, g, bln);
    wq_transpose<<<C, HID>>>();
    transpose_x<<<dim3(N / 64, C / 64, BATCH), 256>>>(x);
    ln_finalize<<<BATCH * N / 256, 256>>>();
    qkv_mma<<<dim3(N / 128, KV_ROWS / 128, BATCH), 256, DSM5_B>>>();
    softmax_k<<<BATCH * HID, 256>>>();
    ctx_partial<<<dim3(NSEG, BATCH * HEADS), 256>>>();
    fold_w<<<dim3(HEADS, BATCH), 256>>>(wout);
    fold_w2<<<dim3(C / 128, C / 128, BATCH), 256, DSM4_B>>>();
    a2b2<<<dim3(C / 8, BATCH), 256>>>();
    final_mma<<<dim3(N / 128, C / 128, BATCH), 256, DSM5_B>>>(bout, x, out);
}

// round 12
// speedup vs baseline: 1.0312x; 1.0312x over previous
#include <cuda_runtime.h>
#include <cuda_bf16.h>
#include <cstdint>

#define BATCH 8
#define C 512
#define N 8192
#define HEADS 8
#define DIM_HEAD 32
#define HID 256
#define QKV_ROWS 768
#define SCALE 0.17677669529663687f
#define EPS 1e-5f
#define NSEG 16
#define CSEG (N / NSEG)

// ---------------- scratch (device globals; allocation-free rule) ------------
__device__ __align__(256) __nv_bfloat16 g_kv[(size_t)BATCH * 512 * N];     // 64 MB
__device__ __align__(256) __nv_bfloat16 g_qT[(size_t)BATCH * N * HID];     // 32 MB
__device__ __align__(256) __nv_bfloat16 g_xT[(size_t)BATCH * N * C];       // 64 MB
__device__ __align__(256) __nv_bfloat16 g_wqkv_bf[QKV_ROWS * C];
__device__ __align__(256) __nv_bfloat16 g_wfold[(size_t)BATCH * C * HID];  // 2 MB
__device__ __align__(256) float g_psum[8][BATCH * N];
__device__ __align__(256) float g_psumsq[8][BATCH * N];
__device__ __align__(256) float g_mu[BATCH * N];
__device__ __align__(256) float g_rstd[BATCH * N];
__device__ __align__(256) float g_Aw[QKV_ROWS];
__device__ __align__(256) float g_Bw[QKV_ROWS];
__device__ __align__(256) float g_kmax[BATCH * HID];
__device__ __align__(256) float g_kinv[BATCH * HID];
__device__ __align__(256) float g_ctxp[(size_t)NSEG * BATCH * HEADS * 1024];

// ---------------- PTX helpers (generic-target safe: sm_80+) -----------------
__device__ __forceinline__ uint32_t smem_u32(const void* p) {
    uint32_t a;
    asm("{ .reg .u64 t; cvta.to.shared.u64 t, %1; cvt.u32.u64 %0, t; }"
        : "=r"(a) : "l"(p));
    return a;
}

__device__ __forceinline__ void cp_async16(uint32_t s, const void* g) {
    asm volatile("cp.async.cg.shared.global [%0], [%1], 16;" :: "r"(s), "l"(g));
}
#define CP_COMMIT asm volatile("cp.async.commit_group;")
#define CP_WAIT3 asm volatile("cp.async.wait_group 3;")
#define CP_WAIT2 asm volatile("cp.async.wait_group 2;")

__device__ __forceinline__ void ldsm4(uint32_t* r, uint32_t addr) {
    asm volatile("ldmatrix.sync.aligned.m8n8.x4.shared.b16 {%0,%1,%2,%3}, [%4];"
                 : "=r"(r[0]), "=r"(r[1]), "=r"(r[2]), "=r"(r[3]) : "r"(addr));
}

__device__ __forceinline__ void mma16816(float* d, const uint32_t* a,
                                         uint32_t b0, uint32_t b1) {
    asm volatile(
        "mma.sync.aligned.m16n8k16.row.col.f32.bf16.bf16.f32 "
        "{%0,%1,%2,%3}, {%4,%5,%6,%7}, {%8,%9}, {%0,%1,%2,%3};"
        : "+f"(d[0]), "+f"(d[1]), "+f"(d[2]), "+f"(d[3])
        : "r"(a[0]), "r"(a[1]), "r"(a[2]), "r"(a[3]), "r"(b0), "r"(b1));
}

#define SPAD 40         // smem row stride (bf16): 80B, conflict-free ldsm
#define STG_E 5120      // per-stage elems: 128*SPAD
#define QSTAGES 5       // qkv pipeline depth
#define FSTAGES 4       // final pipeline depth
#define QKV_DSM_B ((2 * QSTAGES * STG_E) * 2)   // 102400 B
#define FIN_DSM_B ((2 * FSTAGES * STG_E) * 2)   // 81920 B
#define TST 136         // epilogue staging stride

// ---------------------------------------------------------------------------
// 1) fold g into w_qkv -> bf16; A[o]=sum(bf16 wg), B[o]=sum(w*b_ln)
// ---------------------------------------------------------------------------
__global__ __launch_bounds__(256) void prep_w(const float* __restrict__ w,
                                              const float* __restrict__ g,
                                              const float* __restrict__ bln) {
    int o = blockIdx.x;
    int t = threadIdx.x;
    float a = 0.f, bb = 0.f;
    for (int c = t; c < C; c += 256) {
        float wv = w[o * C + c];
        __nv_bfloat16 hb = __float2bfloat16(wv * g[c]);
        g_wqkv_bf[o * C + c] = hb;
        a += __bfloat162float(hb);
        bb += wv * bln[c];
    }
    __shared__ float sa[8], sb[8];
    for (int off = 16; off; off >>= 1) {
        a += __shfl_xor_sync(~0u, a, off);
        bb += __shfl_xor_sync(~0u, bb, off);
    }
    if ((t & 31) == 0) { sa[t >> 5] = a; sb[t >> 5] = bb; }
    __syncthreads();
    if (t == 0) {
        float A = 0.f, Bv = 0.f;
        for (int i = 0; i < 8; i++) { A += sa[i]; Bv += sb[i]; }
        g_Aw[o] = A;
        g_Bw[o] = Bv;
    }
}

// ---------------------------------------------------------------------------
// 2) transpose+convert x -> xT bf16 [b][j][c]  + LN partial sums (fused)
// ---------------------------------------------------------------------------
__global__ __launch_bounds__(256) void transpose_x(const float* __restrict__ x) {
    __shared__ float ts[64][65];
    __shared__ float red[4][64], red2[4][64];
    int b = blockIdx.z, cb = blockIdx.y, j0 = blockIdx.x * 64;
    int c0 = cb * 64;
    int tid = threadIdx.x;
    const float* xb = x + ((size_t)b * C + c0) * N + j0;
#pragma unroll
    for (int it = 0; it < 16; it++) {
        int idx = tid + it * 256;
        int r = idx >> 6, cl = idx & 63;
        ts[r][cl] = xb[(size_t)r * N + cl];
    }
    __syncthreads();
    {
        int p = tid >> 6, jc = tid & 63;
        float s = 0.f, sq = 0.f;
#pragma unroll
        for (int r = 0; r < 16; r++) {
            float v = ts[p * 16 + r][jc];
            s += v;
            sq += v * v;
        }
        red[p][jc] = s;
        red2[p][jc] = sq;
    }
    __syncthreads();
    if (tid < 64) {
        int jc = tid;
        float S = red[0][jc] + red[1][jc] + red[2][jc] + red[3][jc];
        float SQ = red2[0][jc] + red2[1][jc] + red2[2][jc] + red2[3][jc];
        g_psum[cb][b * N + j0 + jc] = S;
        g_psumsq[cb][b * N + j0 + jc] = SQ;
    }
    __nv_bfloat16* ob = g_xT + ((size_t)b * N + j0) * C + c0;
#pragma unroll
    for (int it = 0; it < 2; it++) {
        int u = tid + it * 256;
        int jr = u >> 3, c8 = (u & 7) * 8;
        __nv_bfloat162 tmp[4];
#pragma unroll
        for (int q = 0; q < 4; q++)
            tmp[q] = __floats2bfloat162_rn(ts[c8 + 2 * q][jr], ts[c8 + 2 * q + 1][jr]);
        *(uint4*)(ob + (size_t)jr * C + c8) = *(uint4*)tmp;
    }
}

__global__ __launch_bounds__(256) void ln_finalize() {
    int j = blockIdx.x * 256 + threadIdx.x;
    float s = 0.f, sq = 0.f;
#pragma unroll
    for (int cb = 0; cb < 8; cb++) {
        s += g_psum[cb][j];
        sq += g_psumsq[cb][j];
    }
    float mu = s * (1.0f / C);
    float var = sq * (1.0f / C) - mu * mu;
    g_mu[j] = mu;
    g_rstd[j] = rsqrtf(var + EPS);
}

// ---------------------------------------------------------------------------
// 3) QKV GEMM (R10 winner): CTA 128x128, warp 64x32, 2 CTA/SM, 5 stages.
//    q tiles -> g_qT transposed; k/v tiles -> g_kv row-major.
// ---------------------------------------------------------------------------
__global__ void __launch_bounds__(256, 2) qkv_mma() {
    extern __shared__ __nv_bfloat16 dsm[];
    __nv_bfloat16* Asm = dsm;
    __nv_bfloat16* Bsm = dsm + QSTAGES * STG_E;
    int tid = threadIdx.x, wid = tid >> 5, lane = tid & 31;
    int wm = wid >> 2, wn = wid & 3;
    int b = blockIdx.z, o0 = blockIdx.y * 128, j0 = blockIdx.x * 128;
    const __nv_bfloat16* Ag = g_wqkv_bf + (size_t)o0 * C;
    const __nv_bfloat16* Bg = g_xT + ((size_t)b * N + j0) * C;
    int lrow = tid >> 2, lseg = (tid & 3) * 8;

    float d[4][4][4] = {};
    const int L = C / 32;   // 16

#pragma unroll
    for (int s = 0; s < QSTAGES - 1; s++) {
        int k0 = s * 32;
        cp_async16(smem_u32(Asm + s * STG_E + lrow * SPAD + lseg), Ag + (size_t)lrow * C + k0 + lseg);
        cp_async16(smem_u32(Asm + s * STG_E + (lrow + 64) * SPAD + lseg), Ag + (size_t)(lrow + 64) * C + k0 + lseg);
        cp_async16(smem_u32(Bsm + s * STG_E + lrow * SPAD + lseg), Bg + (size_t)lrow * C + k0 + lseg);
        cp_async16(smem_u32(Bsm + s * STG_E + (lrow + 64) * SPAD + lseg), Bg + (size_t)(lrow + 64) * C + k0 + lseg);
        CP_COMMIT;
    }

    int r = lane & 15;
    uint32_t aB = smem_u32(Asm) + (uint32_t)((wm * 64 + r) * SPAD) * 2 + (lane & 16);
    uint32_t bB = smem_u32(Bsm) + (uint32_t)((wn * 32 + r) * SPAD) * 2 + (lane & 16);

    for (int i = 0; i < L; i++) {
        CP_WAIT3;
        __syncthreads();
        int pf = i + QSTAGES - 1;
        if (pf < L) {
            int k0 = pf * 32;
            int st = pf % QSTAGES;
            cp_async16(smem_u32(Asm + st * STG_E + lrow * SPAD + lseg), Ag + (size_t)lrow * C + k0 + lseg);
            cp_async16(smem_u32(Asm + st * STG_E + (lrow + 64) * SPAD + lseg), Ag + (size_t)(lrow + 64) * C + k0 + lseg);
            cp_async16(smem_u32(Bsm + st * STG_E + lrow * SPAD + lseg), Bg + (size_t)lrow * C + k0 + lseg);
            cp_async16(smem_u32(Bsm + st * STG_E + (lrow + 64) * SPAD + lseg), Bg + (size_t)(lrow + 64) * C + k0 + lseg);
        }
        CP_COMMIT;
        int st = i % QSTAGES;
        uint32_t aS = aB + st * (STG_E * 2);
        uint32_t bS = bB + st * (STG_E * 2);
#pragma unroll
        for (int s = 0; s < 2; s++) {
            uint32_t a[4][4], bb[2][4];
#pragma unroll
            for (int mt = 0; mt < 4; mt++)
                ldsm4(a[mt], aS + mt * (16 * SPAD * 2) + s * 32);
#pragma unroll
            for (int ng = 0; ng < 2; ng++)
                ldsm4(bb[ng], bS + ng * (16 * SPAD * 2) + s * 32);
#pragma unroll
            for (int mt = 0; mt < 4; mt++)
#pragma unroll
                for (int nt = 0; nt < 4; nt++)
                    mma16816(d[mt][nt], a[mt], bb[nt >> 1][nt & 1], bb[nt >> 1][2 + (nt & 1)]);
        }
    }
    __syncthreads();

    // epilogue with folded-LN affine
    int g = lane >> 2, qq = lane & 3;
    const float* mup = g_mu + (size_t)b * N + j0;
    const float* rp = g_rstd + (size_t)b * N + j0;
    bool isq = (o0 < HID);
    float sc = isq ? SCALE : 1.0f;
    __nv_bfloat16* T = dsm;
#pragma unroll
    for (int mt = 0; mt < 4; mt++) {
        int lr = wm * 64 + mt * 16 + g;
        int o_r = o0 + lr;
        float A0 = g_Aw[o_r], B0 = g_Bw[o_r];
        float A1 = g_Aw[o_r + 8], B1 = g_Bw[o_r + 8];
#pragma unroll
        for (int nt = 0; nt < 4; nt++) {
            int jc = wn * 32 + nt * 8 + qq * 2;
            float m0 = mup[jc], m1 = mup[jc + 1];
            float r0 = rp[jc], r1 = rp[jc + 1];
            float v00 = ((d[mt][nt][0] - m0 * A0) * r0 + B0) * sc;
            float v01 = ((d[mt][nt][1] - m1 * A0) * r1 + B0) * sc;
            float v10 = ((d[mt][nt][2] - m0 * A1) * r0 + B1) * sc;
            float v11 = ((d[mt][nt][3] - m1 * A1) * r1 + B1) * sc;
            if (isq) {
                T[jc * TST + lr] = __float2bfloat16(v00);
                T[(jc + 1) * TST + lr] = __float2bfloat16(v01);
                T[jc * TST + lr + 8] = __float2bfloat16(v10);
                T[(jc + 1) * TST + lr + 8] = __float2bfloat16(v11);
            } else {
                *(__nv_bfloat162*)(T + lr * TST + jc) = __floats2bfloat162_rn(v00, v01);
                *(__nv_bfloat162*)(T + (lr + 8) * TST + jc) = __floats2bfloat162_rn(v10, v11);
            }
        }
    }
    __syncthreads();
    if (isq) {
        __nv_bfloat16* outq = g_qT + ((size_t)b * N + j0) * HID + o0;
#pragma unroll
        for (int it = 0; it < 8; it++) {
            int u = tid + it * 256;
            int row = u >> 4, cc = (u & 15) * 8;
            *(uint4*)(outq + (size_t)row * HID + cc) = *(uint4*)(T + row * TST + cc);
        }
    } else {
        __nv_bfloat16* outb = g_kv + (size_t)b * 512 * N + (size_t)(o0 - HID) * N + j0;
#pragma unroll
        for (int it = 0; it < 8; it++) {
            int row = it * 16 + (tid >> 4);
            int cc = (tid & 15) * 8;
            *(uint4*)(outb + (size_t)row * N + cc) = *(uint4*)(T + row * TST + cc);
        }
    }
}

// ---------------------------------------------------------------------------
// 4) k row stats: max and 1/sum(exp) per k row (no write-back of k)
// ---------------------------------------------------------------------------
__global__ __launch_bounds__(256) void k_stats() {
    int row = blockIdx.x;          // 0 .. BATCH*HID-1
    int b = row >> 8;
    int cc = row & 255;
    const __nv_bfloat162* p2 = (const __nv_bfloat162*)(g_kv + ((size_t)b * 512 + cc) * N);
    int t = threadIdx.x;
    float2 v[16];
    float mx = -1e30f;
#pragma unroll
    for (int i = 0; i < 16; i++) {
        v[i] = __bfloat1622float2(p2[t + i * 256]);
        mx = fmaxf(mx, fmaxf(v[i].x, v[i].y));
    }
    __shared__ float sm[8], ss[8];
    for (int off = 16; off; off >>= 1) mx = fmaxf(mx, __shfl_xor_sync(~0u, mx, off));
    if ((t & 31) == 0) sm[t >> 5] = mx;
    __syncthreads();
    mx = sm[0];
#pragma unroll
    for (int w = 1; w < 8; w++) mx = fmaxf(mx, sm[w]);
    float s = 0.f;
#pragma unroll
    for (int i = 0; i < 16; i++)
        s += __expf(v[i].x - mx) + __expf(v[i].y - mx);
    for (int off = 16; off; off >>= 1) s += __shfl_xor_sync(~0u, s, off);
    if ((t & 31) == 0) ss[t >> 5] = s;
    __syncthreads();
    if (t == 0) {
        float tot = 0.f;
#pragma unroll
        for (int w = 0; w < 8; w++) tot += ss[w];
        g_kmax[row] = mx;
        g_kinv[row] = 1.0f / tot;
    }
}

// ---------------------------------------------------------------------------
// 5) context partials — softmax applied on the fly from raw k + row stats
// ---------------------------------------------------------------------------
__global__ __launch_bounds__(256) void ctx_partial() {
    int s = blockIdx.x;
    int bh = blockIdx.y;
    int b = bh >> 3, h = bh & 7;
    const __nv_bfloat16* kb = g_kv + ((size_t)b * 512 + h * 32) * N;
    const __nv_bfloat16* vb = g_kv + ((size_t)b * 512 + 256 + h * 32) * N;
    __shared__ float ks[32][129];
    __shared__ float vs[32][129];
    __shared__ float smax[32], sinv[32];
    int tid = threadIdx.x;
    if (tid < 32) {
        smax[tid] = g_kmax[b * HID + h * 32 + tid];
        sinv[tid] = g_kinv[b * HID + h * 32 + tid];
    }
    __syncthreads();
    int d0 = (tid >> 4) * 2;
    int e0 = (tid & 15) * 2;
    float a00 = 0.f, a01 = 0.f, a10 = 0.f, a11 = 0.f;
    for (int j0 = s * CSEG; j0 < (s + 1) * CSEG; j0 += 128) {
#pragma unroll
        for (int it = 0; it < 2; it++) {
            int u = tid + it * 256;
            int row = u >> 4, c8 = (u & 15) * 8;
            float km = smax[row], ki = sinv[row];
            uint4 kv = *(const uint4*)(kb + (size_t)row * N + j0 + c8);
            uint4 vv = *(const uint4*)(vb + (size_t)row * N + j0 + c8);
            __nv_bfloat162* hk = (__nv_bfloat162*)&kv;
            __nv_bfloat162* hv = (__nv_bfloat162*)&vv;
#pragma unroll
            for (int q = 0; q < 4; q++) {
                float2 fk = __bfloat1622float2(hk[q]);
                float2 fv = __bfloat1622float2(hv[q]);
                ks[row][c8 + 2 * q] = __expf(fk.x - km) * ki;
                ks[row][c8 + 2 * q + 1] = __expf(fk.y - km) * ki;
                vs[row][c8 + 2 * q] = fv.x;
                vs[row][c8 + 2 * q + 1] = fv.y;
            }
        }
        __syncthreads();
#pragma unroll 8
        for (int jj = 0; jj < 128; jj++) {
            float k0v = ks[d0][jj], k1v = ks[d0 + 1][jj];
            float v0v = vs[e0][jj], v1v = vs[e0 + 1][jj];
            a00 += k0v * v0v;
            a01 += k0v * v1v;
            a10 += k1v * v0v;
            a11 += k1v * v1v;
        }
        __syncthreads();
    }
    float* outp = g_ctxp + ((size_t)s * 64 + bh) * 1024;
    outp[d0 * 32 + e0] = a00;
    outp[d0 * 32 + e0 + 1] = a01;
    outp[(d0 + 1) * 32 + e0] = a10;
    outp[(d0 + 1) * 32 + e0 + 1] = a11;
}

// ---------------------------------------------------------------------------
// 6) fold context into output weights (array-free)
// ---------------------------------------------------------------------------
__global__ __launch_bounds__(256) void fold_w(const float* __restrict__ wout) {
    int h = blockIdx.x, b = blockIdx.y;
    int bh = b * 8 + h;
    int tid = threadIdx.x;
    __shared__ float ctx[32][33];
    for (int i = tid; i < 1024; i += 256) {
        float s = 0.f;
#pragma unroll
        for (int sg = 0; sg < NSEG; sg++) s += g_ctxp[((size_t)sg * 64 + bh) * 1024 + i];
        ctx[i >> 5][i & 31] = s;
    }
    __syncthreads();
    int dd = tid & 31;
    for (int o = tid >> 5; o < C; o += 8) {
        const float* wrow = wout + (size_t)o * HID + h * 32;
        float s = 0.f;
#pragma unroll
        for (int e = 0; e < 32; e++) s += wrow[e] * ctx[dd][e];
        g_wfold[((size_t)b * C + o) * HID + h * 32 + dd] = __float2bfloat16(s);
    }
}

// ---------------------------------------------------------------------------
// 7) final GEMM: out = W'[b] . qT + b_out + x   (proven R10 config)
// ---------------------------------------------------------------------------
__global__ void __launch_bounds__(256, 2) final_mma(const float* __restrict__ bout,
                                                    const float* __restrict__ x,
                                                    float* __restrict__ out) {
    extern __shared__ __nv_bfloat16 dsm[];
    __nv_bfloat16* Asm = dsm;
    __nv_bfloat16* Bsm = dsm + FSTAGES * STG_E;
    int tid = threadIdx.x, wid = tid >> 5, lane = tid & 31;
    int wm = wid >> 2, wn = wid & 3;
    int b = blockIdx.z, o0 = blockIdx.y * 128, j0 = blockIdx.x * 128;
    const __nv_bfloat16* Ag = g_wfold + (size_t)b * C * HID + (size_t)o0 * HID;
    const __nv_bfloat16* Bg = g_qT + ((size_t)b * N + j0) * HID;
    int lrow = tid >> 2, lseg = (tid & 3) * 8;

    float d[4][4][4] = {};
    const int L = HID / 32;   // 8

#pragma unroll
    for (int s = 0; s < FSTAGES - 1; s++) {
        int k0 = s * 32;
        cp_async16(smem_u32(Asm + s * STG_E + lrow * SPAD + lseg), Ag + (size_t)lrow * HID + k0 + lseg);
        cp_async16(smem_u32(Asm + s * STG_E + (lrow + 64) * SPAD + lseg), Ag + (size_t)(lrow + 64) * HID + k0 + lseg);
        cp_async16(smem_u32(Bsm + s * STG_E + lrow * SPAD + lseg), Bg + (size_t)lrow * HID + k0 + lseg);
        cp_async16(smem_u32(Bsm + s * STG_E + (lrow + 64) * SPAD + lseg), Bg + (size_t)(lrow + 64) * HID + k0 + lseg);
        CP_COMMIT;
    }

    int r = lane & 15;
    uint32_t aB = smem_u32(Asm) + (uint32_t)((wm * 64 + r) * SPAD) * 2 + (lane & 16);
    uint32_t bB = smem_u32(Bsm) + (uint32_t)((wn * 32 + r) * SPAD) * 2 + (lane & 16);

    for (int i = 0; i < L; i++) {
        CP_WAIT2;
        __syncthreads();
        int pf = i + FSTAGES - 1;
        if (pf < L) {
            int k0 = pf * 32, st = pf & (FSTAGES - 1);
            cp_async16(smem_u32(Asm + st * STG_E + lrow * SPAD + lseg), Ag + (size_t)lrow * HID + k0 + lseg);
            cp_async16(smem_u32(Asm + st * STG_E + (lrow + 64) * SPAD + lseg), Ag + (size_t)(lrow + 64) * HID + k0 + lseg);
            cp_async16(smem_u32(Bsm + st * STG_E + lrow * SPAD + lseg), Bg + (size_t)lrow * HID + k0 + lseg);
            cp_async16(smem_u32(Bsm + st * STG_E + (lrow + 64) * SPAD + lseg), Bg + (size_t)(lrow + 64) * HID + k0 + lseg);
        }
        CP_COMMIT;
        int st = i & (FSTAGES - 1);
        uint32_t aS = aB + st * (STG_E * 2);
        uint32_t bS = bB + st * (STG_E * 2);
#pragma unroll
        for (int s = 0; s < 2; s++) {
            uint32_t a[4][4], bb[2][4];
#pragma unroll
            for (int mt = 0; mt < 4; mt++)
                ldsm4(a[mt], aS + mt * (16 * SPAD * 2) + s * 32);
#pragma unroll
            for (int ng = 0; ng < 2; ng++)
                ldsm4(bb[ng], bS + ng * (16 * SPAD * 2) + s * 32);
#pragma unroll
            for (int mt = 0; mt < 4; mt++)
#pragma unroll
                for (int nt = 0; nt < 4; nt++)
                    mma16816(d[mt][nt], a[mt], bb[nt >> 1][nt & 1], bb[nt >> 1][2 + (nt & 1)]);
        }
    }

    int g = lane >> 2, qq = lane & 3;
    const float* xb = x + (size_t)b * C * N + j0;
    float* ob = out + (size_t)b * C * N + j0;
#pragma unroll
    for (int mt = 0; mt < 4; mt++) {
        int o_r = o0 + wm * 64 + mt * 16 + g;
        float bo0 = bout[o_r], bo1 = bout[o_r + 8];
#pragma unroll
        for (int nt = 0; nt < 4; nt++) {
            int jc = wn * 32 + nt * 8 + qq * 2;
            float2 x0 = *(const float2*)(xb + (size_t)o_r * N + jc);
            float2 x1 = *(const float2*)(xb + (size_t)(o_r + 8) * N + jc);
            float2 v0, v1;
            v0.x = d[mt][nt][0] + bo0 + x0.x;
            v0.y = d[mt][nt][1] + bo0 + x0.y;
            v1.x = d[mt][nt][2] + bo1 + x1.x;
            v1.y = d[mt][nt][3] + bo1 + x1.y;
            *(float2*)(ob + (size_t)o_r * N + jc) = v0;
            *(float2*)(ob + (size_t)(o_r + 8) * N + jc) = v1;
        }
    }
}

// ---------------------------------------------------------------------------
extern "C" void kernel_launch(void* const* d_in, const int* in_sizes, int n_in,
                              void* d_out, int out_size) {
    const float* x = (const float*)d_in[0];
    const float* g = (const float*)d_in[1];
    const float* bln = (const float*)d_in[2];
    const float* wqkv = (const float*)d_in[3];
    const float* wout = (const float*)d_in[4];
    const float* bout = (const float*)d_in[5];
    float* out = (float*)d_out;

    cudaFuncSetAttribute(qkv_mma, cudaFuncAttributeMaxDynamicSharedMemorySize, QKV_DSM_B);
    cudaFuncSetAttribute(final_mma, cudaFuncAttributeMaxDynamicSharedMemorySize, FIN_DSM_B);

    prep_w<<<QKV_ROWS, 256>>>(wqkv, g, bln);
    transpose_x<<<dim3(N / 64, C / 64, BATCH), 256>>>(x);
    ln_finalize<<<BATCH * N / 256, 256>>>();
    qkv_mma<<<dim3(N / 128, QKV_ROWS / 128, BATCH), 256, QKV_DSM_B>>>();
    k_stats<<<BATCH * HID, 256>>>();
    ctx_partial<<<dim3(NSEG, BATCH * HEADS), 256>>>();
    fold_w<<<dim3(HEADS, BATCH), 256>>>(wout);
    final_mma<<<dim3(N / 128, C / 128, BATCH), 256, FIN_DSM_B>>>(bout, x, out);
}

// round 13
// speedup vs baseline: 1.1035x; 1.0701x over previous
#include <cuda_runtime.h>
#include <cuda_bf16.h>
#include <cstdint>

#define BATCH 8
#define C 512
#define N 8192
#define HEADS 8
#define DIM_HEAD 32
#define HID 256
#define QKV_ROWS 768
#define SCALE 0.17677669529663687f
#define EPS 1e-5f
#define NSEG 16
#define CSEG (N / NSEG)

// ---------------- scratch (device globals; allocation-free rule) ------------
__device__ __align__(256) __nv_bfloat16 g_kv[(size_t)BATCH * 512 * N];     // 64 MB
__device__ __align__(256) __nv_bfloat16 g_qT[(size_t)BATCH * N * HID];     // 32 MB
__device__ __align__(256) __nv_bfloat16 g_xT[(size_t)BATCH * N * C];       // 64 MB
__device__ __align__(256) __nv_bfloat16 g_wqkv_bf[QKV_ROWS * C];
__device__ __align__(256) __nv_bfloat16 g_wfold[(size_t)BATCH * C * HID];  // 2 MB
__device__ __align__(256) float g_psum[8][BATCH * N];
__device__ __align__(256) float g_psumsq[8][BATCH * N];
__device__ __align__(256) float g_mu[BATCH * N];
__device__ __align__(256) float g_rstd[BATCH * N];
__device__ __align__(256) float g_Aw[QKV_ROWS];
__device__ __align__(256) float g_Bw[QKV_ROWS];
__device__ __align__(256) float g_kmax[BATCH * HID];
__device__ __align__(256) float g_kinv[BATCH * HID];
__device__ __align__(256) float g_ctxp[(size_t)NSEG * BATCH * HEADS * 1024];

// ---------------- PTX helpers (generic-target safe: sm_80+) -----------------
__device__ __forceinline__ uint32_t smem_u32(const void* p) {
    uint32_t a;
    asm("{ .reg .u64 t; cvta.to.shared.u64 t, %1; cvt.u32.u64 %0, t; }"
        : "=r"(a) : "l"(p));
    return a;
}

__device__ __forceinline__ void cp_async16(uint32_t s, const void* g) {
    asm volatile("cp.async.cg.shared.global [%0], [%1], 16;" :: "r"(s), "l"(g));
}
#define CP_COMMIT asm volatile("cp.async.commit_group;")
#define CP_WAIT3 asm volatile("cp.async.wait_group 3;")
#define CP_WAIT2 asm volatile("cp.async.wait_group 2;")

__device__ __forceinline__ void ldsm4(uint32_t* r, uint32_t addr) {
    asm volatile("ldmatrix.sync.aligned.m8n8.x4.shared.b16 {%0,%1,%2,%3}, [%4];"
                 : "=r"(r[0]), "=r"(r[1]), "=r"(r[2]), "=r"(r[3]) : "r"(addr));
}

__device__ __forceinline__ void mma16816(float* d, const uint32_t* a,
                                         uint32_t b0, uint32_t b1) {
    asm volatile(
        "mma.sync.aligned.m16n8k16.row.col.f32.bf16.bf16.f32 "
        "{%0,%1,%2,%3}, {%4,%5,%6,%7}, {%8,%9}, {%0,%1,%2,%3};"
        : "+f"(d[0]), "+f"(d[1]), "+f"(d[2]), "+f"(d[3])
        : "r"(a[0]), "r"(a[1]), "r"(a[2]), "r"(a[3]), "r"(b0), "r"(b1));
}

#define SPAD 40         // smem row stride (bf16): 80B, conflict-free ldsm
#define STG_E 5120      // per-stage elems: 128*SPAD
#define QSTAGES 5       // qkv pipeline depth
#define FSTAGES 4       // final pipeline depth
#define QKV_DSM_B ((2 * QSTAGES * STG_E) * 2)   // 102400 B
#define FIN_DSM_B ((2 * FSTAGES * STG_E) * 2)   // 81920 B
#define TST 136         // epilogue staging stride

// ---------------------------------------------------------------------------
// 1) fold g into w_qkv -> bf16; A[o]=sum(bf16 wg), B[o]=sum(w*b_ln)
// ---------------------------------------------------------------------------
__global__ __launch_bounds__(256) void prep_w(const float* __restrict__ w,
                                              const float* __restrict__ g,
                                              const float* __restrict__ bln) {
    int o = blockIdx.x;
    int t = threadIdx.x;
    float a = 0.f, bb = 0.f;
    for (int c = t; c < C; c += 256) {
        float wv = w[o * C + c];
        __nv_bfloat16 hb = __float2bfloat16(wv * g[c]);
        g_wqkv_bf[o * C + c] = hb;
        a += __bfloat162float(hb);
        bb += wv * bln[c];
    }
    __shared__ float sa[8], sb[8];
    for (int off = 16; off; off >>= 1) {
        a += __shfl_xor_sync(~0u, a, off);
        bb += __shfl_xor_sync(~0u, bb, off);
    }
    if ((t & 31) == 0) { sa[t >> 5] = a; sb[t >> 5] = bb; }
    __syncthreads();
    if (t == 0) {
        float A = 0.f, Bv = 0.f;
        for (int i = 0; i < 8; i++) { A += sa[i]; Bv += sb[i]; }
        g_Aw[o] = A;
        g_Bw[o] = Bv;
    }
}

// ---------------------------------------------------------------------------
// 2) transpose+convert x -> xT bf16 [b][j][c]  + LN partial sums (fused)
// ---------------------------------------------------------------------------
__global__ __launch_bounds__(256) void transpose_x(const float* __restrict__ x) {
    __shared__ float ts[64][65];
    __shared__ float red[4][64], red2[4][64];
    int b = blockIdx.z, cb = blockIdx.y, j0 = blockIdx.x * 64;
    int c0 = cb * 64;
    int tid = threadIdx.x;
    const float* xb = x + ((size_t)b * C + c0) * N + j0;
#pragma unroll
    for (int it = 0; it < 16; it++) {
        int idx = tid + it * 256;
        int r = idx >> 6, cl = idx & 63;
        ts[r][cl] = xb[(size_t)r * N + cl];
    }
    __syncthreads();
    {
        int p = tid >> 6, jc = tid & 63;
        float s = 0.f, sq = 0.f;
#pragma unroll
        for (int r = 0; r < 16; r++) {
            float v = ts[p * 16 + r][jc];
            s += v;
            sq += v * v;
        }
        red[p][jc] = s;
        red2[p][jc] = sq;
    }
    __syncthreads();
    if (tid < 64) {
        int jc = tid;
        float S = red[0][jc] + red[1][jc] + red[2][jc] + red[3][jc];
        float SQ = red2[0][jc] + red2[1][jc] + red2[2][jc] + red2[3][jc];
        g_psum[cb][b * N + j0 + jc] = S;
        g_psumsq[cb][b * N + j0 + jc] = SQ;
    }
    __nv_bfloat16* ob = g_xT + ((size_t)b * N + j0) * C + c0;
#pragma unroll
    for (int it = 0; it < 2; it++) {
        int u = tid + it * 256;
        int jr = u >> 3, c8 = (u & 7) * 8;
        __nv_bfloat162 tmp[4];
#pragma unroll
        for (int q = 0; q < 4; q++)
            tmp[q] = __floats2bfloat162_rn(ts[c8 + 2 * q][jr], ts[c8 + 2 * q + 1][jr]);
        *(uint4*)(ob + (size_t)jr * C + c8) = *(uint4*)tmp;
    }
}

__global__ __launch_bounds__(256) void ln_finalize() {
    int j = blockIdx.x * 256 + threadIdx.x;
    float s = 0.f, sq = 0.f;
#pragma unroll
    for (int cb = 0; cb < 8; cb++) {
        s += g_psum[cb][j];
        sq += g_psumsq[cb][j];
    }
    float mu = s * (1.0f / C);
    float var = sq * (1.0f / C) - mu * mu;
    g_mu[j] = mu;
    g_rstd[j] = rsqrtf(var + EPS);
}

// ---------------------------------------------------------------------------
// 3) QKV GEMM (R10 winner): CTA 128x128, warp 64x32, 2 CTA/SM, 5 stages.
// ---------------------------------------------------------------------------
__global__ void __launch_bounds__(256, 2) qkv_mma() {
    extern __shared__ __nv_bfloat16 dsm[];
    __nv_bfloat16* Asm = dsm;
    __nv_bfloat16* Bsm = dsm + QSTAGES * STG_E;
    int tid = threadIdx.x, wid = tid >> 5, lane = tid & 31;
    int wm = wid >> 2, wn = wid & 3;
    int b = blockIdx.z, o0 = blockIdx.y * 128, j0 = blockIdx.x * 128;
    const __nv_bfloat16* Ag = g_wqkv_bf + (size_t)o0 * C;
    const __nv_bfloat16* Bg = g_xT + ((size_t)b * N + j0) * C;
    int lrow = tid >> 2, lseg = (tid & 3) * 8;

    float d[4][4][4] = {};
    const int L = C / 32;   // 16

#pragma unroll
    for (int s = 0; s < QSTAGES - 1; s++) {
        int k0 = s * 32;
        cp_async16(smem_u32(Asm + s * STG_E + lrow * SPAD + lseg), Ag + (size_t)lrow * C + k0 + lseg);
        cp_async16(smem_u32(Asm + s * STG_E + (lrow + 64) * SPAD + lseg), Ag + (size_t)(lrow + 64) * C + k0 + lseg);
        cp_async16(smem_u32(Bsm + s * STG_E + lrow * SPAD + lseg), Bg + (size_t)lrow * C + k0 + lseg);
        cp_async16(smem_u32(Bsm + s * STG_E + (lrow + 64) * SPAD + lseg), Bg + (size_t)(lrow + 64) * C + k0 + lseg);
        CP_COMMIT;
    }

    int r = lane & 15;
    uint32_t aB = smem_u32(Asm) + (uint32_t)((wm * 64 + r) * SPAD) * 2 + (lane & 16);
    uint32_t bB = smem_u32(Bsm) + (uint32_t)((wn * 32 + r) * SPAD) * 2 + (lane & 16);

    for (int i = 0; i < L; i++) {
        CP_WAIT3;
        __syncthreads();
        int pf = i + QSTAGES - 1;
        if (pf < L) {
            int k0 = pf * 32;
            int st = pf % QSTAGES;
            cp_async16(smem_u32(Asm + st * STG_E + lrow * SPAD + lseg), Ag + (size_t)lrow * C + k0 + lseg);
            cp_async16(smem_u32(Asm + st * STG_E + (lrow + 64) * SPAD + lseg), Ag + (size_t)(lrow + 64) * C + k0 + lseg);
            cp_async16(smem_u32(Bsm + st * STG_E + lrow * SPAD + lseg), Bg + (size_t)lrow * C + k0 + lseg);
            cp_async16(smem_u32(Bsm + st * STG_E + (lrow + 64) * SPAD + lseg), Bg + (size_t)(lrow + 64) * C + k0 + lseg);
        }
        CP_COMMIT;
        int st = i % QSTAGES;
        uint32_t aS = aB + st * (STG_E * 2);
        uint32_t bS = bB + st * (STG_E * 2);
#pragma unroll
        for (int s = 0; s < 2; s++) {
            uint32_t a[4][4], bb[2][4];
#pragma unroll
            for (int mt = 0; mt < 4; mt++)
                ldsm4(a[mt], aS + mt * (16 * SPAD * 2) + s * 32);
#pragma unroll
            for (int ng = 0; ng < 2; ng++)
                ldsm4(bb[ng], bS + ng * (16 * SPAD * 2) + s * 32);
#pragma unroll
            for (int mt = 0; mt < 4; mt++)
#pragma unroll
                for (int nt = 0; nt < 4; nt++)
                    mma16816(d[mt][nt], a[mt], bb[nt >> 1][nt & 1], bb[nt >> 1][2 + (nt & 1)]);
        }
    }
    __syncthreads();

    // epilogue with folded-LN affine
    int g = lane >> 2, qq = lane & 3;
    const float* mup = g_mu + (size_t)b * N + j0;
    const float* rp = g_rstd + (size_t)b * N + j0;
    bool isq = (o0 < HID);
    float sc = isq ? SCALE : 1.0f;
    __nv_bfloat16* T = dsm;
#pragma unroll
    for (int mt = 0; mt < 4; mt++) {
        int lr = wm * 64 + mt * 16 + g;
        int o_r = o0 + lr;
        float A0 = g_Aw[o_r], B0 = g_Bw[o_r];
        float A1 = g_Aw[o_r + 8], B1 = g_Bw[o_r + 8];
#pragma unroll
        for (int nt = 0; nt < 4; nt++) {
            int jc = wn * 32 + nt * 8 + qq * 2;
            float m0 = mup[jc], m1 = mup[jc + 1];
            float r0 = rp[jc], r1 = rp[jc + 1];
            float v00 = ((d[mt][nt][0] - m0 * A0) * r0 + B0) * sc;
            float v01 = ((d[mt][nt][1] - m1 * A0) * r1 + B0) * sc;
            float v10 = ((d[mt][nt][2] - m0 * A1) * r0 + B1) * sc;
            float v11 = ((d[mt][nt][3] - m1 * A1) * r1 + B1) * sc;
            if (isq) {
                T[jc * TST + lr] = __float2bfloat16(v00);
                T[(jc + 1) * TST + lr] = __float2bfloat16(v01);
                T[jc * TST + lr + 8] = __float2bfloat16(v10);
                T[(jc + 1) * TST + lr + 8] = __float2bfloat16(v11);
            } else {
                *(__nv_bfloat162*)(T + lr * TST + jc) = __floats2bfloat162_rn(v00, v01);
                *(__nv_bfloat162*)(T + (lr + 8) * TST + jc) = __floats2bfloat162_rn(v10, v11);
            }
        }
    }
    __syncthreads();
    if (isq) {
        __nv_bfloat16* outq = g_qT + ((size_t)b * N + j0) * HID + o0;
#pragma unroll
        for (int it = 0; it < 8; it++) {
            int u = tid + it * 256;
            int row = u >> 4, cc = (u & 15) * 8;
            *(uint4*)(outq + (size_t)row * HID + cc) = *(uint4*)(T + row * TST + cc);
        }
    } else {
        __nv_bfloat16* outb = g_kv + (size_t)b * 512 * N + (size_t)(o0 - HID) * N + j0;
#pragma unroll
        for (int it = 0; it < 8; it++) {
            int row = it * 16 + (tid >> 4);
            int cc = (tid & 15) * 8;
            *(uint4*)(outb + (size_t)row * N + cc) = *(uint4*)(T + row * TST + cc);
        }
    }
}

// ---------------------------------------------------------------------------
// 4) k row stats: max and 1/sum(exp) per k row (no write-back of k)
// ---------------------------------------------------------------------------
__global__ __launch_bounds__(256) void k_stats() {
    int row = blockIdx.x;          // 0 .. BATCH*HID-1
    int b = row >> 8;
    int cc = row & 255;
    const __nv_bfloat162* p2 = (const __nv_bfloat162*)(g_kv + ((size_t)b * 512 + cc) * N);
    int t = threadIdx.x;
    float2 v[16];
    float mx = -1e30f;
#pragma unroll
    for (int i = 0; i < 16; i++) {
        v[i] = __bfloat1622float2(p2[t + i * 256]);
        mx = fmaxf(mx, fmaxf(v[i].x, v[i].y));
    }
    __shared__ float sm[8], ss[8];
    for (int off = 16; off; off >>= 1) mx = fmaxf(mx, __shfl_xor_sync(~0u, mx, off));
    if ((t & 31) == 0) sm[t >> 5] = mx;
    __syncthreads();
    mx = sm[0];
#pragma unroll
    for (int w = 1; w < 8; w++) mx = fmaxf(mx, sm[w]);
    float s = 0.f;
#pragma unroll
    for (int i = 0; i < 16; i++)
        s += __expf(v[i].x - mx) + __expf(v[i].y - mx);
    for (int off = 16; off; off >>= 1) s += __shfl_xor_sync(~0u, s, off);
    if ((t & 31) == 0) ss[t >> 5] = s;
    __syncthreads();
    if (t == 0) {
        float tot = 0.f;
#pragma unroll
        for (int w = 0; w < 8; w++) tot += ss[w];
        g_kmax[row] = mx;
        g_kinv[row] = 1.0f / tot;
    }
}

// ---------------------------------------------------------------------------
// 5) context partials — 4x4 per-thread microtile, jj split over 4 groups.
//    softmax applied on the fly from raw k + row stats.
// ---------------------------------------------------------------------------
__global__ __launch_bounds__(256) void ctx_partial() {
    int s = blockIdx.x;
    int bh = blockIdx.y;
    int b = bh >> 3, h = bh & 7;
    const __nv_bfloat16* kb = g_kv + ((size_t)b * 512 + h * 32) * N;
    const __nv_bfloat16* vb = g_kv + ((size_t)b * 512 + 256 + h * 32) * N;
    __shared__ float ks[32][129];
    __shared__ float vs[32][129];
    __shared__ float smax[32], sinv[32];
    int tid = threadIdx.x;
    if (tid < 32) {
        smax[tid] = g_kmax[b * HID + h * 32 + tid];
        sinv[tid] = g_kinv[b * HID + h * 32 + tid];
    }
    __syncthreads();
    int grp = tid >> 6;            // 0..3: jj quarter within each 128-tile
    int t = tid & 63;
    int d0 = (t >> 3) * 4;         // 0,4,...,28
    int e0 = (t & 7) * 4;          // 0,4,...,28
    float acc[4][4] = {};
    for (int j0 = s * CSEG; j0 < (s + 1) * CSEG; j0 += 128) {
#pragma unroll
        for (int it = 0; it < 2; it++) {
            int u = tid + it * 256;
            int row = u >> 4, c8 = (u & 15) * 8;
            float km = smax[row], ki = sinv[row];
            uint4 kv = *(const uint4*)(kb + (size_t)row * N + j0 + c8);
            uint4 vv = *(const uint4*)(vb + (size_t)row * N + j0 + c8);
            __nv_bfloat162* hk = (__nv_bfloat162*)&kv;
            __nv_bfloat162* hv = (__nv_bfloat162*)&vv;
#pragma unroll
            for (int q = 0; q < 4; q++) {
                float2 fk = __bfloat1622float2(hk[q]);
                float2 fv = __bfloat1622float2(hv[q]);
                ks[row][c8 + 2 * q] = __expf(fk.x - km) * ki;
                ks[row][c8 + 2 * q + 1] = __expf(fk.y - km) * ki;
                vs[row][c8 + 2 * q] = fv.x;
                vs[row][c8 + 2 * q + 1] = fv.y;
            }
        }
        __syncthreads();
        int jbase = grp * 32;
#pragma unroll 8
        for (int jo = 0; jo < 32; jo++) {
            int jj = jbase + jo;
            float kf[4], vf[4];
#pragma unroll
            for (int i = 0; i < 4; i++) kf[i] = ks[d0 + i][jj];
#pragma unroll
            for (int q = 0; q < 4; q++) vf[q] = vs[e0 + q][jj];
#pragma unroll
            for (int i = 0; i < 4; i++)
#pragma unroll
                for (int q = 0; q < 4; q++)
                    acc[i][q] += kf[i] * vf[q];
        }
        __syncthreads();
    }
    // cross-group reduction: alias partial store into ks (4128 floats >= 4096)
    float* red = &ks[0][0];
#pragma unroll
    for (int i = 0; i < 4; i++)
#pragma unroll
        for (int q = 0; q < 4; q++)
            red[grp * 1024 + (d0 + i) * 32 + e0 + q] = acc[i][q];
    __syncthreads();
    float* outp = g_ctxp + ((size_t)s * 64 + bh) * 1024;
    for (int idx = tid; idx < 1024; idx += 256)
        outp[idx] = red[idx] + red[1024 + idx] + red[2048 + idx] + red[3072 + idx];
}

// ---------------------------------------------------------------------------
// 6) fold context into output weights (array-free)
// ---------------------------------------------------------------------------
__global__ __launch_bounds__(256) void fold_w(const float* __restrict__ wout) {
    int h = blockIdx.x, b = blockIdx.y;
    int bh = b * 8 + h;
    int tid = threadIdx.x;
    __shared__ float ctx[32][33];
    for (int i = tid; i < 1024; i += 256) {
        float s = 0.f;
#pragma unroll
        for (int sg = 0; sg < NSEG; sg++) s += g_ctxp[((size_t)sg * 64 + bh) * 1024 + i];
        ctx[i >> 5][i & 31] = s;
    }
    __syncthreads();
    int dd = tid & 31;
    for (int o = tid >> 5; o < C; o += 8) {
        const float* wrow = wout + (size_t)o * HID + h * 32;
        float s = 0.f;
#pragma unroll
        for (int e = 0; e < 32; e++) s += wrow[e] * ctx[dd][e];
        g_wfold[((size_t)b * C + o) * HID + h * 32 + dd] = __float2bfloat16(s);
    }
}

// ---------------------------------------------------------------------------
// 7) final GEMM: out = W'[b] . qT + b_out + x   (proven R10 config)
// ---------------------------------------------------------------------------
__global__ void __launch_bounds__(256, 2) final_mma(const float* __restrict__ bout,
                                                    const float* __restrict__ x,
                                                    float* __restrict__ out) {
    extern __shared__ __nv_bfloat16 dsm[];
    __nv_bfloat16* Asm = dsm;
    __nv_bfloat16* Bsm = dsm + FSTAGES * STG_E;
    int tid = threadIdx.x, wid = tid >> 5, lane = tid & 31;
    int wm = wid >> 2, wn = wid & 3;
    int b = blockIdx.z, o0 = blockIdx.y * 128, j0 = blockIdx.x * 128;
    const __nv_bfloat16* Ag = g_wfold + (size_t)b * C * HID + (size_t)o0 * HID;
    const __nv_bfloat16* Bg = g_qT + ((size_t)b * N + j0) * HID;
    int lrow = tid >> 2, lseg = (tid & 3) * 8;

    float d[4][4][4] = {};
    const int L = HID / 32;   // 8

#pragma unroll
    for (int s = 0; s < FSTAGES - 1; s++) {
        int k0 = s * 32;
        cp_async16(smem_u32(Asm + s * STG_E + lrow * SPAD + lseg), Ag + (size_t)lrow * HID + k0 + lseg);
        cp_async16(smem_u32(Asm + s * STG_E + (lrow + 64) * SPAD + lseg), Ag + (size_t)(lrow + 64) * HID + k0 + lseg);
        cp_async16(smem_u32(Bsm + s * STG_E + lrow * SPAD + lseg), Bg + (size_t)lrow * HID + k0 + lseg);
        cp_async16(smem_u32(Bsm + s * STG_E + (lrow + 64) * SPAD + lseg), Bg + (size_t)(lrow + 64) * HID + k0 + lseg);
        CP_COMMIT;
    }

    int r = lane & 15;
    uint32_t aB = smem_u32(Asm) + (uint32_t)((wm * 64 + r) * SPAD) * 2 + (lane & 16);
    uint32_t bB = smem_u32(Bsm) + (uint32_t)((wn * 32 + r) * SPAD) * 2 + (lane & 16);

    for (int i = 0; i < L; i++) {
        CP_WAIT2;
        __syncthreads();
        int pf = i + FSTAGES - 1;
        if (pf < L) {
            int k0 = pf * 32, st = pf & (FSTAGES - 1);
            cp_async16(smem_u32(Asm + st * STG_E + lrow * SPAD + lseg), Ag + (size_t)lrow * HID + k0 + lseg);
            cp_async16(smem_u32(Asm + st * STG_E + (lrow + 64) * SPAD + lseg), Ag + (size_t)(lrow + 64) * HID + k0 + lseg);
            cp_async16(smem_u32(Bsm + st * STG_E + lrow * SPAD + lseg), Bg + (size_t)lrow * HID + k0 + lseg);
            cp_async16(smem_u32(Bsm + st * STG_E + (lrow + 64) * SPAD + lseg), Bg + (size_t)(lrow + 64) * HID + k0 + lseg);
        }
        CP_COMMIT;
        int st = i & (FSTAGES - 1);
        uint32_t aS = aB + st * (STG_E * 2);
        uint32_t bS = bB + st * (STG_E * 2);
#pragma unroll
        for (int s = 0; s < 2; s++) {
            uint32_t a[4][4], bb[2][4];
#pragma unroll
            for (int mt = 0; mt < 4; mt++)
                ldsm4(a[mt], aS + mt * (16 * SPAD * 2) + s * 32);
#pragma unroll
            for (int ng = 0; ng < 2; ng++)
                ldsm4(bb[ng], bS + ng * (16 * SPAD * 2) + s * 32);
#pragma unroll
            for (int mt = 0; mt < 4; mt++)
#pragma unroll
                for (int nt = 0; nt < 4; nt++)
                    mma16816(d[mt][nt], a[mt], bb[nt >> 1][nt & 1], bb[nt >> 1][2 + (nt & 1)]);
        }
    }

    int g = lane >> 2, qq = lane & 3;
    const float* xb = x + (size_t)b * C * N + j0;
    float* ob = out + (size_t)b * C * N + j0;
#pragma unroll
    for (int mt = 0; mt < 4; mt++) {
        int o_r = o0 + wm * 64 + mt * 16 + g;
        float bo0 = bout[o_r], bo1 = bout[o_r + 8];
#pragma unroll
        for (int nt = 0; nt < 4; nt++) {
            int jc = wn * 32 + nt * 8 + qq * 2;
            float2 x0 = *(const float2*)(xb + (size_t)o_r * N + jc);
            float2 x1 = *(const float2*)(xb + (size_t)(o_r + 8) * N + jc);
            float2 v0, v1;
            v0.x = d[mt][nt][0] + bo0 + x0.x;
            v0.y = d[mt][nt][1] + bo0 + x0.y;
            v1.x = d[mt][nt][2] + bo1 + x1.x;
            v1.y = d[mt][nt][3] + bo1 + x1.y;
            *(float2*)(ob + (size_t)o_r * N + jc) = v0;
            *(float2*)(ob + (size_t)(o_r + 8) * N + jc) = v1;
        }
    }
}

// ---------------------------------------------------------------------------
extern "C" void kernel_launch(void* const* d_in, const int* in_sizes, int n_in,
                              void* d_out, int out_size) {
    const float* x = (const float*)d_in[0];
    const float* g = (const float*)d_in[1];
    const float* bln = (const float*)d_in[2];
    const float* wqkv = (const float*)d_in[3];
    const float* wout = (const float*)d_in[4];
    const float* bout = (const float*)d_in[5];
    float* out = (float*)d_out;

    cudaFuncSetAttribute(qkv_mma, cudaFuncAttributeMaxDynamicSharedMemorySize, QKV_DSM_B);
    cudaFuncSetAttribute(final_mma, cudaFuncAttributeMaxDynamicSharedMemorySize, FIN_DSM_B);

    prep_w<<<QKV_ROWS, 256>>>(wqkv, g, bln);
    transpose_x<<<dim3(N / 64, C / 64, BATCH), 256>>>(x);
    ln_finalize<<<BATCH * N / 256, 256>>>();
    qkv_mma<<<dim3(N / 128, QKV_ROWS / 128, BATCH), 256, QKV_DSM_B>>>();
    k_stats<<<BATCH * HID, 256>>>();
    ctx_partial<<<dim3(NSEG, BATCH * HEADS), 256>>>();
    fold_w<<<dim3(HEADS, BATCH), 256>>>(wout);
    final_mma<<<dim3(N / 128, C / 128, BATCH), 256, FIN_DSM_B>>>(bout, x, out);
}

// round 14
// speedup vs baseline: 1.1193x; 1.0144x over previous
#include <cuda_runtime.h>
#include <cuda_bf16.h>
#include <cstdint>

#define BATCH 8
#define C 512
#define N 8192
#define HEADS 8
#define DIM_HEAD 32
#define HID 256
#define QKV_ROWS 768
#define SCALE 0.17677669529663687f
#define EPS 1e-5f
#define NSEG 16
#define CSEG (N / NSEG)
#define NJT (N / 128)   // 64 j-tiles

// ---------------- scratch (device globals; allocation-free rule) ------------
__device__ __align__(256) __nv_bfloat16 g_kv[(size_t)BATCH * 512 * N];     // 64 MB
__device__ __align__(256) __nv_bfloat16 g_qT[(size_t)BATCH * N * HID];     // 32 MB
__device__ __align__(256) __nv_bfloat16 g_xT[(size_t)BATCH * N * C];       // 64 MB
__device__ __align__(256) __nv_bfloat16 g_wqkv_bf[QKV_ROWS * C];
__device__ __align__(256) __nv_bfloat16 g_wfold[(size_t)BATCH * C * HID];  // 2 MB
__device__ __align__(256) float g_psum[8][BATCH * N];
__device__ __align__(256) float g_psumsq[8][BATCH * N];
__device__ __align__(256) float g_mu[BATCH * N];
__device__ __align__(256) float g_rstd[BATCH * N];
__device__ __align__(256) float g_Aw[QKV_ROWS];
__device__ __align__(256) float g_Bw[QKV_ROWS];
__device__ __align__(256) float g_kpmax[BATCH * HID * NJT];
__device__ __align__(256) float g_kpsum[BATCH * HID * NJT];
__device__ __align__(256) float g_kmax[BATCH * HID];
__device__ __align__(256) float g_kinv[BATCH * HID];
__device__ __align__(256) float g_ctxp[(size_t)NSEG * BATCH * HEADS * 1024];

// ---------------- PTX helpers (generic-target safe: sm_80+) -----------------
__device__ __forceinline__ uint32_t smem_u32(const void* p) {
    uint32_t a;
    asm("{ .reg .u64 t; cvta.to.shared.u64 t, %1; cvt.u32.u64 %0, t; }"
        : "=r"(a) : "l"(p));
    return a;
}

__device__ __forceinline__ void cp_async16(uint32_t s, const void* g) {
    asm volatile("cp.async.cg.shared.global [%0], [%1], 16;" :: "r"(s), "l"(g));
}
#define CP_COMMIT asm volatile("cp.async.commit_group;")
#define CP_WAIT3 asm volatile("cp.async.wait_group 3;")
#define CP_WAIT2 asm volatile("cp.async.wait_group 2;")

__device__ __forceinline__ void ldsm4(uint32_t* r, uint32_t addr) {
    asm volatile("ldmatrix.sync.aligned.m8n8.x4.shared.b16 {%0,%1,%2,%3}, [%4];"
                 : "=r"(r[0]), "=r"(r[1]), "=r"(r[2]), "=r"(r[3]) : "r"(addr));
}

__device__ __forceinline__ void mma16816(float* d, const uint32_t* a,
                                         uint32_t b0, uint32_t b1) {
    asm volatile(
        "mma.sync.aligned.m16n8k16.row.col.f32.bf16.bf16.f32 "
        "{%0,%1,%2,%3}, {%4,%5,%6,%7}, {%8,%9}, {%0,%1,%2,%3};"
        : "+f"(d[0]), "+f"(d[1]), "+f"(d[2]), "+f"(d[3])
        : "r"(a[0]), "r"(a[1]), "r"(a[2]), "r"(a[3]), "r"(b0), "r"(b1));
}

#define SPAD 40         // smem row stride (bf16): 80B, conflict-free ldsm
#define STG_E 5120      // per-stage elems: 128*SPAD
#define QSTAGES 5       // qkv pipeline depth
#define FSTAGES 4       // final pipeline depth
#define QKV_DSM_B ((2 * QSTAGES * STG_E) * 2)   // 102400 B
#define FIN_DSM_B ((2 * FSTAGES * STG_E) * 2)   // 81920 B
#define TST 136         // epilogue staging stride

// ---------------------------------------------------------------------------
// 1) fold g into w_qkv -> bf16; A[o]=sum(bf16 wg), B[o]=sum(w*b_ln)
// ---------------------------------------------------------------------------
__global__ __launch_bounds__(256) void prep_w(const float* __restrict__ w,
                                              const float* __restrict__ g,
                                              const float* __restrict__ bln) {
    int o = blockIdx.x;
    int t = threadIdx.x;
    float a = 0.f, bb = 0.f;
    for (int c = t; c < C; c += 256) {
        float wv = w[o * C + c];
        __nv_bfloat16 hb = __float2bfloat16(wv * g[c]);
        g_wqkv_bf[o * C + c] = hb;
        a += __bfloat162float(hb);
        bb += wv * bln[c];
    }
    __shared__ float sa[8], sb[8];
    for (int off = 16; off; off >>= 1) {
        a += __shfl_xor_sync(~0u, a, off);
        bb += __shfl_xor_sync(~0u, bb, off);
    }
    if ((t & 31) == 0) { sa[t >> 5] = a; sb[t >> 5] = bb; }
    __syncthreads();
    if (t == 0) {
        float A = 0.f, Bv = 0.f;
        for (int i = 0; i < 8; i++) { A += sa[i]; Bv += sb[i]; }
        g_Aw[o] = A;
        g_Bw[o] = Bv;
    }
}

// ---------------------------------------------------------------------------
// 2) transpose+convert x -> xT bf16 [b][j][c]  + LN partial sums (fused)
//    float4 global loads, scalar smem stores (conflict-free [64][65])
// ---------------------------------------------------------------------------
__global__ __launch_bounds__(256) void transpose_x(const float* __restrict__ x) {
    __shared__ float ts[64][65];
    __shared__ float red[4][64], red2[4][64];
    int b = blockIdx.z, cb = blockIdx.y, j0 = blockIdx.x * 64;
    int c0 = cb * 64;
    int tid = threadIdx.x;
    const float* xb = x + ((size_t)b * C + c0) * N + j0;
#pragma unroll
    for (int it = 0; it < 4; it++) {
        int idx = tid + it * 256;             // 1024 float4
        int r = idx >> 4, c4 = (idx & 15) * 4;
        float4 v = *(const float4*)(xb + (size_t)r * N + c4);
        ts[r][c4] = v.x;
        ts[r][c4 + 1] = v.y;
        ts[r][c4 + 2] = v.z;
        ts[r][c4 + 3] = v.w;
    }
    __syncthreads();
    {
        int p = tid >> 6, jc = tid & 63;
        float s = 0.f, sq = 0.f;
#pragma unroll
        for (int r = 0; r < 16; r++) {
            float v = ts[p * 16 + r][jc];
            s += v;
            sq += v * v;
        }
        red[p][jc] = s;
        red2[p][jc] = sq;
    }
    __syncthreads();
    if (tid < 64) {
        int jc = tid;
        float S = red[0][jc] + red[1][jc] + red[2][jc] + red[3][jc];
        float SQ = red2[0][jc] + red2[1][jc] + red2[2][jc] + red2[3][jc];
        g_psum[cb][b * N + j0 + jc] = S;
        g_psumsq[cb][b * N + j0 + jc] = SQ;
    }
    __nv_bfloat16* ob = g_xT + ((size_t)b * N + j0) * C + c0;
#pragma unroll
    for (int it = 0; it < 2; it++) {
        int u = tid + it * 256;
        int jr = u >> 3, c8 = (u & 7) * 8;
        __nv_bfloat162 tmp[4];
#pragma unroll
        for (int q = 0; q < 4; q++)
            tmp[q] = __floats2bfloat162_rn(ts[c8 + 2 * q][jr], ts[c8 + 2 * q + 1][jr]);
        *(uint4*)(ob + (size_t)jr * C + c8) = *(uint4*)tmp;
    }
}

__global__ __launch_bounds__(256) void ln_finalize() {
    int j = blockIdx.x * 256 + threadIdx.x;
    float s = 0.f, sq = 0.f;
#pragma unroll
    for (int cb = 0; cb < 8; cb++) {
        s += g_psum[cb][j];
        sq += g_psumsq[cb][j];
    }
    float mu = s * (1.0f / C);
    float var = sq * (1.0f / C) - mu * mu;
    g_mu[j] = mu;
    g_rstd[j] = rsqrtf(var + EPS);
}

// ---------------------------------------------------------------------------
// 3) QKV GEMM (R10 winner) + fused per-tile k-softmax partial stats
// ---------------------------------------------------------------------------
__global__ void __launch_bounds__(256, 2) qkv_mma() {
    extern __shared__ __nv_bfloat16 dsm[];
    __nv_bfloat16* Asm = dsm;
    __nv_bfloat16* Bsm = dsm + QSTAGES * STG_E;
    int tid = threadIdx.x, wid = tid >> 5, lane = tid & 31;
    int wm = wid >> 2, wn = wid & 3;
    int b = blockIdx.z, o0 = blockIdx.y * 128, j0 = blockIdx.x * 128;
    const __nv_bfloat16* Ag = g_wqkv_bf + (size_t)o0 * C;
    const __nv_bfloat16* Bg = g_xT + ((size_t)b * N + j0) * C;
    int lrow = tid >> 2, lseg = (tid & 3) * 8;

    float d[4][4][4] = {};
    const int L = C / 32;   // 16

#pragma unroll
    for (int s = 0; s < QSTAGES - 1; s++) {
        int k0 = s * 32;
        cp_async16(smem_u32(Asm + s * STG_E + lrow * SPAD + lseg), Ag + (size_t)lrow * C + k0 + lseg);
        cp_async16(smem_u32(Asm + s * STG_E + (lrow + 64) * SPAD + lseg), Ag + (size_t)(lrow + 64) * C + k0 + lseg);
        cp_async16(smem_u32(Bsm + s * STG_E + lrow * SPAD + lseg), Bg + (size_t)lrow * C + k0 + lseg);
        cp_async16(smem_u32(Bsm + s * STG_E + (lrow + 64) * SPAD + lseg), Bg + (size_t)(lrow + 64) * C + k0 + lseg);
        CP_COMMIT;
    }

    int r = lane & 15;
    uint32_t aB = smem_u32(Asm) + (uint32_t)((wm * 64 + r) * SPAD) * 2 + (lane & 16);
    uint32_t bB = smem_u32(Bsm) + (uint32_t)((wn * 32 + r) * SPAD) * 2 + (lane & 16);

    for (int i = 0; i < L; i++) {
        CP_WAIT3;
        __syncthreads();
        int pf = i + QSTAGES - 1;
        if (pf < L) {
            int k0 = pf * 32;
            int st = pf % QSTAGES;
            cp_async16(smem_u32(Asm + st * STG_E + lrow * SPAD + lseg), Ag + (size_t)lrow * C + k0 + lseg);
            cp_async16(smem_u32(Asm + st * STG_E + (lrow + 64) * SPAD + lseg), Ag + (size_t)(lrow + 64) * C + k0 + lseg);
            cp_async16(smem_u32(Bsm + st * STG_E + lrow * SPAD + lseg), Bg + (size_t)lrow * C + k0 + lseg);
            cp_async16(smem_u32(Bsm + st * STG_E + (lrow + 64) * SPAD + lseg), Bg + (size_t)(lrow + 64) * C + k0 + lseg);
        }
        CP_COMMIT;
        int st = i % QSTAGES;
        uint32_t aS = aB + st * (STG_E * 2);
        uint32_t bS = bB + st * (STG_E * 2);
#pragma unroll
        for (int s = 0; s < 2; s++) {
            uint32_t a[4][4], bb[2][4];
#pragma unroll
            for (int mt = 0; mt < 4; mt++)
                ldsm4(a[mt], aS + mt * (16 * SPAD * 2) + s * 32);
#pragma unroll
            for (int ng = 0; ng < 2; ng++)
                ldsm4(bb[ng], bS + ng * (16 * SPAD * 2) + s * 32);
#pragma unroll
            for (int mt = 0; mt < 4; mt++)
#pragma unroll
                for (int nt = 0; nt < 4; nt++)
                    mma16816(d[mt][nt], a[mt], bb[nt >> 1][nt & 1], bb[nt >> 1][2 + (nt & 1)]);
        }
    }
    __syncthreads();

    // epilogue with folded-LN affine
    int g = lane >> 2, qq = lane & 3;
    const float* mup = g_mu + (size_t)b * N + j0;
    const float* rp = g_rstd + (size_t)b * N + j0;
    bool isq = (o0 < HID);
    float sc = isq ? SCALE : 1.0f;
    __nv_bfloat16* T = dsm;
#pragma unroll
    for (int mt = 0; mt < 4; mt++) {
        int lr = wm * 64 + mt * 16 + g;
        int o_r = o0 + lr;
        float A0 = g_Aw[o_r], B0 = g_Bw[o_r];
        float A1 = g_Aw[o_r + 8], B1 = g_Bw[o_r + 8];
#pragma unroll
        for (int nt = 0; nt < 4; nt++) {
            int jc = wn * 32 + nt * 8 + qq * 2;
            float m0 = mup[jc], m1 = mup[jc + 1];
            float r0 = rp[jc], r1 = rp[jc + 1];
            float v00 = ((d[mt][nt][0] - m0 * A0) * r0 + B0) * sc;
            float v01 = ((d[mt][nt][1] - m1 * A0) * r1 + B0) * sc;
            float v10 = ((d[mt][nt][2] - m0 * A1) * r0 + B1) * sc;
            float v11 = ((d[mt][nt][3] - m1 * A1) * r1 + B1) * sc;
            if (isq) {
                T[jc * TST + lr] = __float2bfloat16(v00);
                T[(jc + 1) * TST + lr] = __float2bfloat16(v01);
                T[jc * TST + lr + 8] = __float2bfloat16(v10);
                T[(jc + 1) * TST + lr + 8] = __float2bfloat16(v11);
            } else {
                *(__nv_bfloat162*)(T + lr * TST + jc) = __floats2bfloat162_rn(v00, v01);
                *(__nv_bfloat162*)(T + (lr + 8) * TST + jc) = __floats2bfloat162_rn(v10, v11);
            }
        }
    }
    __syncthreads();
    if (isq) {
        __nv_bfloat16* outq = g_qT + ((size_t)b * N + j0) * HID + o0;
#pragma unroll
        for (int it = 0; it < 8; it++) {
            int u = tid + it * 256;
            int row = u >> 4, cc = (u & 15) * 8;
            *(uint4*)(outq + (size_t)row * HID + cc) = *(uint4*)(T + row * TST + cc);
        }
    } else {
        __nv_bfloat16* outb = g_kv + (size_t)b * 512 * N + (size_t)(o0 - HID) * N + j0;
#pragma unroll
        for (int it = 0; it < 8; it++) {
            int row = it * 16 + (tid >> 4);
            int cc = (tid & 15) * 8;
            *(uint4*)(outb + (size_t)row * N + cc) = *(uint4*)(T + row * TST + cc);
        }
        // fused k-softmax partial stats (k rows only: o0 in [256, 512))
        if (o0 < 2 * HID) {
            int row = tid >> 1, half = tid & 1;
            const __nv_bfloat16* tr = T + row * TST + half * 64;
            uint4 buf[8];
#pragma unroll
            for (int i = 0; i < 8; i++) buf[i] = *(const uint4*)(tr + i * 8);
            float mx = -1e30f;
#pragma unroll
            for (int i = 0; i < 8; i++) {
                __nv_bfloat162* h2 = (__nv_bfloat162*)&buf[i];
#pragma unroll
                for (int q = 0; q < 4; q++) {
                    float2 f = __bfloat1622float2(h2[q]);
                    mx = fmaxf(mx, fmaxf(f.x, f.y));
                }
            }
            mx = fmaxf(mx, __shfl_xor_sync(~0u, mx, 1));
            float s = 0.f;
#pragma unroll
            for (int i = 0; i < 8; i++) {
                __nv_bfloat162* h2 = (__nv_bfloat162*)&buf[i];
#pragma unroll
                for (int q = 0; q < 4; q++) {
                    float2 f = __bfloat1622float2(h2[q]);
                    s += __expf(f.x - mx) + __expf(f.y - mx);
                }
            }
            s += __shfl_xor_sync(~0u, s, 1);
            if (half == 0) {
                int krow = (o0 - HID) + row;
                int jt = j0 >> 7;
                g_kpmax[((size_t)b * HID + krow) * NJT + jt] = mx;
                g_kpsum[((size_t)b * HID + krow) * NJT + jt] = s;
            }
        }
    }
}

// ---------------------------------------------------------------------------
// 4) merge per-tile k stats -> g_kmax, g_kinv (online-softmax merge)
// ---------------------------------------------------------------------------
__global__ __launch_bounds__(256) void k_merge() {
    int row = blockIdx.x * 8 + (threadIdx.x >> 5);   // 0 .. BATCH*HID-1
    int lane = threadIdx.x & 31;
    const float* pm = g_kpmax + (size_t)row * NJT;
    const float* ps = g_kpsum + (size_t)row * NJT;
    float m0 = pm[lane], m1 = pm[32 + lane];
    float s0 = ps[lane], s1 = ps[32 + lane];
    float mx = fmaxf(m0, m1);
    for (int off = 16; off; off >>= 1) mx = fmaxf(mx, __shfl_xor_sync(~0u, mx, off));
    float s = s0 * __expf(m0 - mx) + s1 * __expf(m1 - mx);
    for (int off = 16; off; off >>= 1) s += __shfl_xor_sync(~0u, s, off);
    if (lane == 0) {
        g_kmax[row] = mx;
        g_kinv[row] = 1.0f / s;
    }
}

// ---------------------------------------------------------------------------
// 5) context partials — 4x4 per-thread microtile, jj split over 4 groups.
// ---------------------------------------------------------------------------
__global__ __launch_bounds__(256) void ctx_partial() {
    int s = blockIdx.x;
    int bh = blockIdx.y;
    int b = bh >> 3, h = bh & 7;
    const __nv_bfloat16* kb = g_kv + ((size_t)b * 512 + h * 32) * N;
    const __nv_bfloat16* vb = g_kv + ((size_t)b * 512 + 256 + h * 32) * N;
    __shared__ float ks[32][129];
    __shared__ float vs[32][129];
    __shared__ float smax[32], sinv[32];
    int tid = threadIdx.x;
    if (tid < 32) {
        smax[tid] = g_kmax[b * HID + h * 32 + tid];
        sinv[tid] = g_kinv[b * HID + h * 32 + tid];
    }
    __syncthreads();
    int grp = tid >> 6;
    int t = tid & 63;
    int d0 = (t >> 3) * 4;
    int e0 = (t & 7) * 4;
    float acc[4][4] = {};
    for (int j0 = s * CSEG; j0 < (s + 1) * CSEG; j0 += 128) {
#pragma unroll
        for (int it = 0; it < 2; it++) {
            int u = tid + it * 256;
            int row = u >> 4, c8 = (u & 15) * 8;
            float km = smax[row], ki = sinv[row];
            uint4 kv = *(const uint4*)(kb + (size_t)row * N + j0 + c8);
            uint4 vv = *(const uint4*)(vb + (size_t)row * N + j0 + c8);
            __nv_bfloat162* hk = (__nv_bfloat162*)&kv;
            __nv_bfloat162* hv = (__nv_bfloat162*)&vv;
#pragma unroll
            for (int q = 0; q < 4; q++) {
                float2 fk = __bfloat1622float2(hk[q]);
                float2 fv = __bfloat1622float2(hv[q]);
                ks[row][c8 + 2 * q] = __expf(fk.x - km) * ki;
                ks[row][c8 + 2 * q + 1] = __expf(fk.y - km) * ki;
                vs[row][c8 + 2 * q] = fv.x;
                vs[row][c8 + 2 * q + 1] = fv.y;
            }
        }
        __syncthreads();
        int jbase = grp * 32;
#pragma unroll 8
        for (int jo = 0; jo < 32; jo++) {
            int jj = jbase + jo;
            float kf[4], vf[4];
#pragma unroll
            for (int i = 0; i < 4; i++) kf[i] = ks[d0 + i][jj];
#pragma unroll
            for (int q = 0; q < 4; q++) vf[q] = vs[e0 + q][jj];
#pragma unroll
            for (int i = 0; i < 4; i++)
#pragma unroll
                for (int q = 0; q < 4; q++)
                    acc[i][q] += kf[i] * vf[q];
        }
        __syncthreads();
    }
    float* red = &ks[0][0];
#pragma unroll
    for (int i = 0; i < 4; i++)
#pragma unroll
        for (int q = 0; q < 4; q++)
            red[grp * 1024 + (d0 + i) * 32 + e0 + q] = acc[i][q];
    __syncthreads();
    float* outp = g_ctxp + ((size_t)s * 64 + bh) * 1024;
    for (int idx = tid; idx < 1024; idx += 256)
        outp[idx] = red[idx] + red[1024 + idx] + red[2048 + idx] + red[3072 + idx];
}

// ---------------------------------------------------------------------------
// 6) fold context into output weights (array-free)
// ---------------------------------------------------------------------------
__global__ __launch_bounds__(256) void fold_w(const float* __restrict__ wout) {
    int h = blockIdx.x, b = blockIdx.y;
    int bh = b * 8 + h;
    int tid = threadIdx.x;
    __shared__ float ctx[32][33];
    for (int i = tid; i < 1024; i += 256) {
        float s = 0.f;
#pragma unroll
        for (int sg = 0; sg < NSEG; sg++) s += g_ctxp[((size_t)sg * 64 + bh) * 1024 + i];
        ctx[i >> 5][i & 31] = s;
    }
    __syncthreads();
    int dd = tid & 31;
    for (int o = tid >> 5; o < C; o += 8) {
        const float* wrow = wout + (size_t)o * HID + h * 32;
        float s = 0.f;
#pragma unroll
        for (int e = 0; e < 32; e++) s += wrow[e] * ctx[dd][e];
        g_wfold[((size_t)b * C + o) * HID + h * 32 + dd] = __float2bfloat16(s);
    }
}

// ---------------------------------------------------------------------------
// 7) final GEMM: out = W'[b] . qT + b_out + x   (proven R10 config)
// ---------------------------------------------------------------------------
__global__ void __launch_bounds__(256, 2) final_mma(const float* __restrict__ bout,
                                                    const float* __restrict__ x,
                                                    float* __restrict__ out) {
    extern __shared__ __nv_bfloat16 dsm[];
    __nv_bfloat16* Asm = dsm;
    __nv_bfloat16* Bsm = dsm + FSTAGES * STG_E;
    int tid = threadIdx.x, wid = tid >> 5, lane = tid & 31;
    int wm = wid >> 2, wn = wid & 3;
    int b = blockIdx.z, o0 = blockIdx.y * 128, j0 = blockIdx.x * 128;
    const __nv_bfloat16* Ag = g_wfold + (size_t)b * C * HID + (size_t)o0 * HID;
    const __nv_bfloat16* Bg = g_qT + ((size_t)b * N + j0) * HID;
    int lrow = tid >> 2, lseg = (tid & 3) * 8;

    float d[4][4][4] = {};
    const int L = HID / 32;   // 8

#pragma unroll
    for (int s = 0; s < FSTAGES - 1; s++) {
        int k0 = s * 32;
        cp_async16(smem_u32(Asm + s * STG_E + lrow * SPAD + lseg), Ag + (size_t)lrow * HID + k0 + lseg);
        cp_async16(smem_u32(Asm + s * STG_E + (lrow + 64) * SPAD + lseg), Ag + (size_t)(lrow + 64) * HID + k0 + lseg);
        cp_async16(smem_u32(Bsm + s * STG_E + lrow * SPAD + lseg), Bg + (size_t)lrow * HID + k0 + lseg);
        cp_async16(smem_u32(Bsm + s * STG_E + (lrow + 64) * SPAD + lseg), Bg + (size_t)(lrow + 64) * HID + k0 + lseg);
        CP_COMMIT;
    }

    int r = lane & 15;
    uint32_t aB = smem_u32(Asm) + (uint32_t)((wm * 64 + r) * SPAD) * 2 + (lane & 16);
    uint32_t bB = smem_u32(Bsm) + (uint32_t)((wn * 32 + r) * SPAD) * 2 + (lane & 16);

    for (int i = 0; i < L; i++) {
        CP_WAIT2;
        __syncthreads();
        int pf = i + FSTAGES - 1;
        if (pf < L) {
            int k0 = pf * 32, st = pf & (FSTAGES - 1);
            cp_async16(smem_u32(Asm + st * STG_E + lrow * SPAD + lseg), Ag + (size_t)lrow * HID + k0 + lseg);
            cp_async16(smem_u32(Asm + st * STG_E + (lrow + 64) * SPAD + lseg), Ag + (size_t)(lrow + 64) * HID + k0 + lseg);
            cp_async16(smem_u32(Bsm + st * STG_E + lrow * SPAD + lseg), Bg + (size_t)lrow * HID + k0 + lseg);
            cp_async16(smem_u32(Bsm + st * STG_E + (lrow + 64) * SPAD + lseg), Bg + (size_t)(lrow + 64) * HID + k0 + lseg);
        }
        CP_COMMIT;
        int st = i & (FSTAGES - 1);
        uint32_t aS = aB + st * (STG_E * 2);
        uint32_t bS = bB + st * (STG_E * 2);
#pragma unroll
        for (int s = 0; s < 2; s++) {
            uint32_t a[4][4], bb[2][4];
#pragma unroll
            for (int mt = 0; mt < 4; mt++)
                ldsm4(a[mt], aS + mt * (16 * SPAD * 2) + s * 32);
#pragma unroll
            for (int ng = 0; ng < 2; ng++)
                ldsm4(bb[ng], bS + ng * (16 * SPAD * 2) + s * 32);
#pragma unroll
            for (int mt = 0; mt < 4; mt++)
#pragma unroll
                for (int nt = 0; nt < 4; nt++)
                    mma16816(d[mt][nt], a[mt], bb[nt >> 1][nt & 1], bb[nt >> 1][2 + (nt & 1)]);
        }
    }

    int g = lane >> 2, qq = lane & 3;
    const float* xb = x + (size_t)b * C * N + j0;
    float* ob = out + (size_t)b * C * N + j0;
#pragma unroll
    for (int mt = 0; mt < 4; mt++) {
        int o_r = o0 + wm * 64 + mt * 16 + g;
        float bo0 = bout[o_r], bo1 = bout[o_r + 8];
#pragma unroll
        for (int nt = 0; nt < 4; nt++) {
            int jc = wn * 32 + nt * 8 + qq * 2;
            float2 x0 = *(const float2*)(xb + (size_t)o_r * N + jc);
            float2 x1 = *(const float2*)(xb + (size_t)(o_r + 8) * N + jc);
            float2 v0, v1;
            v0.x = d[mt][nt][0] + bo0 + x0.x;
            v0.y = d[mt][nt][1] + bo0 + x0.y;
            v1.x = d[mt][nt][2] + bo1 + x1.x;
            v1.y = d[mt][nt][3] + bo1 + x1.y;
            *(float2*)(ob + (size_t)o_r * N + jc) = v0;
            *(float2*)(ob + (size_t)(o_r + 8) * N + jc) = v1;
        }
    }
}

// ---------------------------------------------------------------------------
extern "C" void kernel_launch(void* const* d_in, const int* in_sizes, int n_in,
                              void* d_out, int out_size) {
    const float* x = (const float*)d_in[0];
    const float* g = (const float*)d_in[1];
    const float* bln = (const float*)d_in[2];
    const float* wqkv = (const float*)d_in[3];
    const float* wout = (const float*)d_in[4];
    const float* bout = (const float*)d_in[5];
    float* out = (float*)d_out;

    cudaFuncSetAttribute(qkv_mma, cudaFuncAttributeMaxDynamicSharedMemorySize, QKV_DSM_B);
    cudaFuncSetAttribute(final_mma, cudaFuncAttributeMaxDynamicSharedMemorySize, FIN_DSM_B);

    prep_w<<<QKV_ROWS, 256>>>(wqkv, g, bln);
    transpose_x<<<dim3(N / 64, C / 64, BATCH), 256>>>(x);
    ln_finalize<<<BATCH * N / 256, 256>>>();
    qkv_mma<<<dim3(N / 128, QKV_ROWS / 128, BATCH), 256, QKV_DSM_B>>>();
    k_merge<<<BATCH * HID / 8, 256>>>();
    ctx_partial<<<dim3(NSEG, BATCH * HEADS), 256>>>();
    fold_w<<<dim3(HEADS, BATCH), 256>>>(wout);
    final_mma<<<dim3(N / 128, C / 128, BATCH), 256, FIN_DSM_B>>>(bout, x, out);
}

// round 15
// speedup vs baseline: 1.1756x; 1.0502x over previous
#include <cuda_runtime.h>
#include <cuda_bf16.h>
#include <cstdint>

#define BATCH 8
#define C 512
#define N 8192
#define HEADS 8
#define DIM_HEAD 32
#define HID 256
#define QKV_ROWS 768
#define SCALE 0.17677669529663687f
#define EPS 1e-5f
#define NSEG 16
#define CSEG (N / NSEG)
#define NJT (N / 128)   // 64 j-tiles

// ---------------- scratch (device globals; allocation-free rule) ------------
__device__ __align__(256) __nv_bfloat16 g_kv[(size_t)BATCH * 512 * N];     // 64 MB
__device__ __align__(256) __nv_bfloat16 g_qT[(size_t)BATCH * N * HID];     // 32 MB
__device__ __align__(256) __nv_bfloat16 g_xT[(size_t)BATCH * N * C];       // 64 MB
__device__ __align__(256) __nv_bfloat16 g_wqkv_bf[QKV_ROWS * C];
__device__ __align__(256) __nv_bfloat16 g_wfold[(size_t)BATCH * C * HID];  // 2 MB
__device__ __align__(256) float g_psum[8][BATCH * N];
__device__ __align__(256) float g_psumsq[8][BATCH * N];
__device__ __align__(256) float g_mu[BATCH * N];
__device__ __align__(256) float g_rstd[BATCH * N];
__device__ __align__(256) float g_Aw[QKV_ROWS];
__device__ __align__(256) float g_Bw[QKV_ROWS];
__device__ __align__(256) float g_kpmax[BATCH * HID * NJT];
__device__ __align__(256) float g_kpsum[BATCH * HID * NJT];
__device__ __align__(256) float g_kmax[BATCH * HID];
__device__ __align__(256) float g_kinv[BATCH * HID];
__device__ __align__(256) float g_ctxp[(size_t)NSEG * BATCH * HEADS * 1024];

// ---------------- PTX helpers (generic-target safe: sm_80+) -----------------
__device__ __forceinline__ uint32_t smem_u32(const void* p) {
    uint32_t a;
    asm("{ .reg .u64 t; cvta.to.shared.u64 t, %1; cvt.u32.u64 %0, t; }"
        : "=r"(a) : "l"(p));
    return a;
}

__device__ __forceinline__ void cp_async16(uint32_t s, const void* g) {
    asm volatile("cp.async.cg.shared.global [%0], [%1], 16;" :: "r"(s), "l"(g));
}
#define CP_COMMIT asm volatile("cp.async.commit_group;")
#define CP_WAIT3 asm volatile("cp.async.wait_group 3;")
#define CP_WAIT2 asm volatile("cp.async.wait_group 2;")

__device__ __forceinline__ void ldsm4(uint32_t* r, uint32_t addr) {
    asm volatile("ldmatrix.sync.aligned.m8n8.x4.shared.b16 {%0,%1,%2,%3}, [%4];"
                 : "=r"(r[0]), "=r"(r[1]), "=r"(r[2]), "=r"(r[3]) : "r"(addr));
}

__device__ __forceinline__ void mma16816(float* d, const uint32_t* a,
                                         uint32_t b0, uint32_t b1) {
    asm volatile(
        "mma.sync.aligned.m16n8k16.row.col.f32.bf16.bf16.f32 "
        "{%0,%1,%2,%3}, {%4,%5,%6,%7}, {%8,%9}, {%0,%1,%2,%3};"
        : "+f"(d[0]), "+f"(d[1]), "+f"(d[2]), "+f"(d[3])
        : "r"(a[0]), "r"(a[1]), "r"(a[2]), "r"(a[3]), "r"(b0), "r"(b1));
}

#define SPAD 40         // smem row stride (bf16): 80B, conflict-free ldsm
#define STG_E 5120      // per-stage elems: 128*SPAD
#define QSTAGES 5       // qkv pipeline depth
#define FSTAGES 4       // final pipeline depth
#define QKV_DSM_B ((2 * QSTAGES * STG_E) * 2)   // 102400 B
#define FIN_DSM_B ((2 * FSTAGES * STG_E) * 2)   // 81920 B
#define TST 136         // epilogue staging stride
#define CST 136         // ctx tile stride (272B rows: conflict-free ldsm)

// ---------------------------------------------------------------------------
// 1) fold g into w_qkv -> bf16; A[o]=sum(bf16 wg), B[o]=sum(w*b_ln)
// ---------------------------------------------------------------------------
__global__ __launch_bounds__(256) void prep_w(const float* __restrict__ w,
                                              const float* __restrict__ g,
                                              const float* __restrict__ bln) {
    int o = blockIdx.x;
    int t = threadIdx.x;
    float a = 0.f, bb = 0.f;
    for (int c = t; c < C; c += 256) {
        float wv = w[o * C + c];
        __nv_bfloat16 hb = __float2bfloat16(wv * g[c]);
        g_wqkv_bf[o * C + c] = hb;
        a += __bfloat162float(hb);
        bb += wv * bln[c];
    }
    __shared__ float sa[8], sb[8];
    for (int off = 16; off; off >>= 1) {
        a += __shfl_xor_sync(~0u, a, off);
        bb += __shfl_xor_sync(~0u, bb, off);
    }
    if ((t & 31) == 0) { sa[t >> 5] = a; sb[t >> 5] = bb; }
    __syncthreads();
    if (t == 0) {
        float A = 0.f, Bv = 0.f;
        for (int i = 0; i < 8; i++) { A += sa[i]; Bv += sb[i]; }
        g_Aw[o] = A;
        g_Bw[o] = Bv;
    }
}

// ---------------------------------------------------------------------------
// 2) transpose+convert x -> xT bf16 [b][j][c]  + LN partial sums (fused)
// ---------------------------------------------------------------------------
__global__ __launch_bounds__(256) void transpose_x(const float* __restrict__ x) {
    __shared__ float ts[64][65];
    __shared__ float red[4][64], red2[4][64];
    int b = blockIdx.z, cb = blockIdx.y, j0 = blockIdx.x * 64;
    int c0 = cb * 64;
    int tid = threadIdx.x;
    const float* xb = x + ((size_t)b * C + c0) * N + j0;
#pragma unroll
    for (int it = 0; it < 4; it++) {
        int idx = tid + it * 256;
        int r = idx >> 4, c4 = (idx & 15) * 4;
        float4 v = *(const float4*)(xb + (size_t)r * N + c4);
        ts[r][c4] = v.x;
        ts[r][c4 + 1] = v.y;
        ts[r][c4 + 2] = v.z;
        ts[r][c4 + 3] = v.w;
    }
    __syncthreads();
    {
        int p = tid >> 6, jc = tid & 63;
        float s = 0.f, sq = 0.f;
#pragma unroll
        for (int r = 0; r < 16; r++) {
            float v = ts[p * 16 + r][jc];
            s += v;
            sq += v * v;
        }
        red[p][jc] = s;
        red2[p][jc] = sq;
    }
    __syncthreads();
    if (tid < 64) {
        int jc = tid;
        float S = red[0][jc] + red[1][jc] + red[2][jc] + red[3][jc];
        float SQ = red2[0][jc] + red2[1][jc] + red2[2][jc] + red2[3][jc];
        g_psum[cb][b * N + j0 + jc] = S;
        g_psumsq[cb][b * N + j0 + jc] = SQ;
    }
    __nv_bfloat16* ob = g_xT + ((size_t)b * N + j0) * C + c0;
#pragma unroll
    for (int it = 0; it < 2; it++) {
        int u = tid + it * 256;
        int jr = u >> 3, c8 = (u & 7) * 8;
        __nv_bfloat162 tmp[4];
#pragma unroll
        for (int q = 0; q < 4; q++)
            tmp[q] = __floats2bfloat162_rn(ts[c8 + 2 * q][jr], ts[c8 + 2 * q + 1][jr]);
        *(uint4*)(ob + (size_t)jr * C + c8) = *(uint4*)tmp;
    }
}

__global__ __launch_bounds__(256) void ln_finalize() {
    int j = blockIdx.x * 256 + threadIdx.x;
    float s = 0.f, sq = 0.f;
#pragma unroll
    for (int cb = 0; cb < 8; cb++) {
        s += g_psum[cb][j];
        sq += g_psumsq[cb][j];
    }
    float mu = s * (1.0f / C);
    float var = sq * (1.0f / C) - mu * mu;
    g_mu[j] = mu;
    g_rstd[j] = rsqrtf(var + EPS);
}

// ---------------------------------------------------------------------------
// 3) QKV GEMM (R10 winner) + fused per-tile k-softmax partial stats
// ---------------------------------------------------------------------------
__global__ void __launch_bounds__(256, 2) qkv_mma() {
    extern __shared__ __nv_bfloat16 dsm[];
    __nv_bfloat16* Asm = dsm;
    __nv_bfloat16* Bsm = dsm + QSTAGES * STG_E;
    int tid = threadIdx.x, wid = tid >> 5, lane = tid & 31;
    int wm = wid >> 2, wn = wid & 3;
    int b = blockIdx.z, o0 = blockIdx.y * 128, j0 = blockIdx.x * 128;
    const __nv_bfloat16* Ag = g_wqkv_bf + (size_t)o0 * C;
    const __nv_bfloat16* Bg = g_xT + ((size_t)b * N + j0) * C;
    int lrow = tid >> 2, lseg = (tid & 3) * 8;

    float d[4][4][4] = {};
    const int L = C / 32;   // 16

#pragma unroll
    for (int s = 0; s < QSTAGES - 1; s++) {
        int k0 = s * 32;
        cp_async16(smem_u32(Asm + s * STG_E + lrow * SPAD + lseg), Ag + (size_t)lrow * C + k0 + lseg);
        cp_async16(smem_u32(Asm + s * STG_E + (lrow + 64) * SPAD + lseg), Ag + (size_t)(lrow + 64) * C + k0 + lseg);
        cp_async16(smem_u32(Bsm + s * STG_E + lrow * SPAD + lseg), Bg + (size_t)lrow * C + k0 + lseg);
        cp_async16(smem_u32(Bsm + s * STG_E + (lrow + 64) * SPAD + lseg), Bg + (size_t)(lrow + 64) * C + k0 + lseg);
        CP_COMMIT;
    }

    int r = lane & 15;
    uint32_t aB = smem_u32(Asm) + (uint32_t)((wm * 64 + r) * SPAD) * 2 + (lane & 16);
    uint32_t bB = smem_u32(Bsm) + (uint32_t)((wn * 32 + r) * SPAD) * 2 + (lane & 16);

    for (int i = 0; i < L; i++) {
        CP_WAIT3;
        __syncthreads();
        int pf = i + QSTAGES - 1;
        if (pf < L) {
            int k0 = pf * 32;
            int st = pf % QSTAGES;
            cp_async16(smem_u32(Asm + st * STG_E + lrow * SPAD + lseg), Ag + (size_t)lrow * C + k0 + lseg);
            cp_async16(smem_u32(Asm + st * STG_E + (lrow + 64) * SPAD + lseg), Ag + (size_t)(lrow + 64) * C + k0 + lseg);
            cp_async16(smem_u32(Bsm + st * STG_E + lrow * SPAD + lseg), Bg + (size_t)lrow * C + k0 + lseg);
            cp_async16(smem_u32(Bsm + st * STG_E + (lrow + 64) * SPAD + lseg), Bg + (size_t)(lrow + 64) * C + k0 + lseg);
        }
        CP_COMMIT;
        int st = i % QSTAGES;
        uint32_t aS = aB + st * (STG_E * 2);
        uint32_t bS = bB + st * (STG_E * 2);
#pragma unroll
        for (int s = 0; s < 2; s++) {
            uint32_t a[4][4], bb[2][4];
#pragma unroll
            for (int mt = 0; mt < 4; mt++)
                ldsm4(a[mt], aS + mt * (16 * SPAD * 2) + s * 32);
#pragma unroll
            for (int ng = 0; ng < 2; ng++)
                ldsm4(bb[ng], bS + ng * (16 * SPAD * 2) + s * 32);
#pragma unroll
            for (int mt = 0; mt < 4; mt++)
#pragma unroll
                for (int nt = 0; nt < 4; nt++)
                    mma16816(d[mt][nt], a[mt], bb[nt >> 1][nt & 1], bb[nt >> 1][2 + (nt & 1)]);
        }
    }
    __syncthreads();

    // epilogue with folded-LN affine
    int g = lane >> 2, qq = lane & 3;
    const float* mup = g_mu + (size_t)b * N + j0;
    const float* rp = g_rstd + (size_t)b * N + j0;
    bool isq = (o0 < HID);
    float sc = isq ? SCALE : 1.0f;
    __nv_bfloat16* T = dsm;
#pragma unroll
    for (int mt = 0; mt < 4; mt++) {
        int lr = wm * 64 + mt * 16 + g;
        int o_r = o0 + lr;
        float A0 = g_Aw[o_r], B0 = g_Bw[o_r];
        float A1 = g_Aw[o_r + 8], B1 = g_Bw[o_r + 8];
#pragma unroll
        for (int nt = 0; nt < 4; nt++) {
            int jc = wn * 32 + nt * 8 + qq * 2;
            float m0 = mup[jc], m1 = mup[jc + 1];
            float r0 = rp[jc], r1 = rp[jc + 1];
            float v00 = ((d[mt][nt][0] - m0 * A0) * r0 + B0) * sc;
            float v01 = ((d[mt][nt][1] - m1 * A0) * r1 + B0) * sc;
            float v10 = ((d[mt][nt][2] - m0 * A1) * r0 + B1) * sc;
            float v11 = ((d[mt][nt][3] - m1 * A1) * r1 + B1) * sc;
            if (isq) {
                T[jc * TST + lr] = __float2bfloat16(v00);
                T[(jc + 1) * TST + lr] = __float2bfloat16(v01);
                T[jc * TST + lr + 8] = __float2bfloat16(v10);
                T[(jc + 1) * TST + lr + 8] = __float2bfloat16(v11);
            } else {
                *(__nv_bfloat162*)(T + lr * TST + jc) = __floats2bfloat162_rn(v00, v01);
                *(__nv_bfloat162*)(T + (lr + 8) * TST + jc) = __floats2bfloat162_rn(v10, v11);
            }
        }
    }
    __syncthreads();
    if (isq) {
        __nv_bfloat16* outq = g_qT + ((size_t)b * N + j0) * HID + o0;
#pragma unroll
        for (int it = 0; it < 8; it++) {
            int u = tid + it * 256;
            int row = u >> 4, cc = (u & 15) * 8;
            *(uint4*)(outq + (size_t)row * HID + cc) = *(uint4*)(T + row * TST + cc);
        }
    } else {
        __nv_bfloat16* outb = g_kv + (size_t)b * 512 * N + (size_t)(o0 - HID) * N + j0;
#pragma unroll
        for (int it = 0; it < 8; it++) {
            int row = it * 16 + (tid >> 4);
            int cc = (tid & 15) * 8;
            *(uint4*)(outb + (size_t)row * N + cc) = *(uint4*)(T + row * TST + cc);
        }
        if (o0 < 2 * HID) {
            int row = tid >> 1, half = tid & 1;
            const __nv_bfloat16* tr = T + row * TST + half * 64;
            uint4 buf[8];
#pragma unroll
            for (int i = 0; i < 8; i++) buf[i] = *(const uint4*)(tr + i * 8);
            float mx = -1e30f;
#pragma unroll
            for (int i = 0; i < 8; i++) {
                __nv_bfloat162* h2 = (__nv_bfloat162*)&buf[i];
#pragma unroll
                for (int q = 0; q < 4; q++) {
                    float2 f = __bfloat1622float2(h2[q]);
                    mx = fmaxf(mx, fmaxf(f.x, f.y));
                }
            }
            mx = fmaxf(mx, __shfl_xor_sync(~0u, mx, 1));
            float s = 0.f;
#pragma unroll
            for (int i = 0; i < 8; i++) {
                __nv_bfloat162* h2 = (__nv_bfloat162*)&buf[i];
#pragma unroll
                for (int q = 0; q < 4; q++) {
                    float2 f = __bfloat1622float2(h2[q]);
                    s += __expf(f.x - mx) + __expf(f.y - mx);
                }
            }
            s += __shfl_xor_sync(~0u, s, 1);
            if (half == 0) {
                int krow = (o0 - HID) + row;
                int jt = j0 >> 7;
                g_kpmax[((size_t)b * HID + krow) * NJT + jt] = mx;
                g_kpsum[((size_t)b * HID + krow) * NJT + jt] = s;
            }
        }
    }
}

// ---------------------------------------------------------------------------
// 4) merge per-tile k stats -> g_kmax, g_kinv (online-softmax merge)
// ---------------------------------------------------------------------------
__global__ __launch_bounds__(256) void k_merge() {
    int row = blockIdx.x * 8 + (threadIdx.x >> 5);
    int lane = threadIdx.x & 31;
    const float* pm = g_kpmax + (size_t)row * NJT;
    const float* ps = g_kpsum + (size_t)row * NJT;
    float m0 = pm[lane], m1 = pm[32 + lane];
    float s0 = ps[lane], s1 = ps[32 + lane];
    float mx = fmaxf(m0, m1);
    for (int off = 16; off; off >>= 1) mx = fmaxf(mx, __shfl_xor_sync(~0u, mx, off));
    float s = s0 * __expf(m0 - mx) + s1 * __expf(m1 - mx);
    for (int off = 16; off; off >>= 1) s += __shfl_xor_sync(~0u, s, off);
    if (lane == 0) {
        g_kmax[row] = mx;
        g_kinv[row] = 1.0f / s;
    }
}

// ---------------------------------------------------------------------------
// 5) context partials via mma.sync: each warp owns a 16-wide k-slice of each
//    128-j chunk; expk staged bf16 (stride CST), v copied raw; cross-warp
//    register-partial reduction through smem at the end.
// ---------------------------------------------------------------------------
__global__ __launch_bounds__(256) void ctx_partial() {
    int s = blockIdx.x;
    int bh = blockIdx.y;
    int b = bh >> 3, h = bh & 7;
    const __nv_bfloat16* kb = g_kv + ((size_t)b * 512 + h * 32) * N;
    const __nv_bfloat16* vb = g_kv + ((size_t)b * 512 + 256 + h * 32) * N;
    __shared__ __align__(16) char usm[33792];           // union: tiles | red
    __nv_bfloat16 (*ek)[CST] = (__nv_bfloat16(*)[CST])usm;           // 8704 B
    __nv_bfloat16 (*vs)[CST] = (__nv_bfloat16(*)[CST])(usm + 8704);  // 8704 B
    float* smax = (float*)(usm + 17408);
    float* sinv = smax + 32;
    int tid = threadIdx.x, wid = tid >> 5, lane = tid & 31;
    if (tid < 32) {
        smax[tid] = g_kmax[b * HID + h * 32 + tid];
        sinv[tid] = g_kinv[b * HID + h * 32 + tid];
    }
    __syncthreads();

    float d[2][4][4] = {};
    int r = lane & 15;
    uint32_t aB = smem_u32(&ek[0][0]) + (uint32_t)r * (CST * 2) + (lane & 16) + wid * 32;
    uint32_t bB = smem_u32(&vs[0][0]) + (uint32_t)r * (CST * 2) + (lane & 16) + wid * 32;

    for (int j0 = s * CSEG; j0 < (s + 1) * CSEG; j0 += 128) {
#pragma unroll
        for (int it = 0; it < 2; it++) {
            int u = tid + it * 256;
            int row = u >> 4, c8 = (u & 15) * 8;
            float km = smax[row], ki = sinv[row];
            uint4 kvv = *(const uint4*)(kb + (size_t)row * N + j0 + c8);
            __nv_bfloat162* hk = (__nv_bfloat162*)&kvv;
            __nv_bfloat162 outk[4];
#pragma unroll
            for (int q = 0; q < 4; q++) {
                float2 fk = __bfloat1622float2(hk[q]);
                outk[q] = __floats2bfloat162_rn(__expf(fk.x - km) * ki,
                                                __expf(fk.y - km) * ki);
            }
            *(uint4*)(&ek[row][c8]) = *(uint4*)outk;
            *(uint4*)(&vs[row][c8]) = *(const uint4*)(vb + (size_t)row * N + j0 + c8);
        }
        __syncthreads();
        uint32_t a0[4], a1[4], b0f[4], b1f[4];
        ldsm4(a0, aB);
        ldsm4(a1, aB + 16 * (CST * 2));
        ldsm4(b0f, bB);
        ldsm4(b1f, bB + 16 * (CST * 2));
#pragma unroll
        for (int nt = 0; nt < 4; nt++) {
            uint32_t f0 = (nt < 2) ? b0f[nt & 1] : b1f[nt & 1];
            uint32_t f1 = (nt < 2) ? b0f[2 + (nt & 1)] : b1f[2 + (nt & 1)];
            mma16816(d[0][nt], a0, f0, f1);
            mma16816(d[1][nt], a1, f0, f1);
        }
        __syncthreads();
    }

    // cross-warp reduction through smem (stride 33 rows: conflict-light)
    float* red = (float*)usm;    // [8][1056]
    int g = lane >> 2, qq = lane & 3;
#pragma unroll
    for (int mt = 0; mt < 2; mt++)
#pragma unroll
        for (int nt = 0; nt < 4; nt++) {
            int m0 = mt * 16 + g, n0 = nt * 8 + qq * 2;
            red[wid * 1056 + m0 * 33 + n0] = d[mt][nt][0];
            red[wid * 1056 + m0 * 33 + n0 + 1] = d[mt][nt][1];
            red[wid * 1056 + (m0 + 8) * 33 + n0] = d[mt][nt][2];
            red[wid * 1056 + (m0 + 8) * 33 + n0 + 1] = d[mt][nt][3];
        }
    __syncthreads();
    float* outp = g_ctxp + ((size_t)s * 64 + bh) * 1024;
    for (int idx = tid; idx < 1024; idx += 256) {
        int m = idx >> 5, n = idx & 31;
        float t = 0.f;
#pragma unroll
        for (int w = 0; w < 8; w++) t += red[w * 1056 + m * 33 + n];
        outp[idx] = t;
    }
}

// ---------------------------------------------------------------------------
// 6) fold context into output weights (array-free)
// ---------------------------------------------------------------------------
__global__ __launch_bounds__(256) void fold_w(const float* __restrict__ wout) {
    int h = blockIdx.x, b = blockIdx.y;
    int bh = b * 8 + h;
    int tid = threadIdx.x;
    __shared__ float ctx[32][33];
    for (int i = tid; i < 1024; i += 256) {
        float s = 0.f;
#pragma unroll
        for (int sg = 0; sg < NSEG; sg++) s += g_ctxp[((size_t)sg * 64 + bh) * 1024 + i];
        ctx[i >> 5][i & 31] = s;
    }
    __syncthreads();
    int dd = tid & 31;
    for (int o = tid >> 5; o < C; o += 8) {
        const float* wrow = wout + (size_t)o * HID + h * 32;
        float s = 0.f;
#pragma unroll
        for (int e = 0; e < 32; e++) s += wrow[e] * ctx[dd][e];
        g_wfold[((size_t)b * C + o) * HID + h * 32 + dd] = __float2bfloat16(s);
    }
}

// ---------------------------------------------------------------------------
// 7) final GEMM: out = W'[b] . qT + b_out + x   (proven R10 config)
// ---------------------------------------------------------------------------
__global__ void __launch_bounds__(256, 2) final_mma(const float* __restrict__ bout,
                                                    const float* __restrict__ x,
                                                    float* __restrict__ out) {
    extern __shared__ __nv_bfloat16 dsm[];
    __nv_bfloat16* Asm = dsm;
    __nv_bfloat16* Bsm = dsm + FSTAGES * STG_E;
    int tid = threadIdx.x, wid = tid >> 5, lane = tid & 31;
    int wm = wid >> 2, wn = wid & 3;
    int b = blockIdx.z, o0 = blockIdx.y * 128, j0 = blockIdx.x * 128;
    const __nv_bfloat16* Ag = g_wfold + (size_t)b * C * HID + (size_t)o0 * HID;
    const __nv_bfloat16* Bg = g_qT + ((size_t)b * N + j0) * HID;
    int lrow = tid >> 2, lseg = (tid & 3) * 8;

    float d[4][4][4] = {};
    const int L = HID / 32;   // 8

#pragma unroll
    for (int s = 0; s < FSTAGES - 1; s++) {
        int k0 = s * 32;
        cp_async16(smem_u32(Asm + s * STG_E + lrow * SPAD + lseg), Ag + (size_t)lrow * HID + k0 + lseg);
        cp_async16(smem_u32(Asm + s * STG_E + (lrow + 64) * SPAD + lseg), Ag + (size_t)(lrow + 64) * HID + k0 + lseg);
        cp_async16(smem_u32(Bsm + s * STG_E + lrow * SPAD + lseg), Bg + (size_t)lrow * HID + k0 + lseg);
        cp_async16(smem_u32(Bsm + s * STG_E + (lrow + 64) * SPAD + lseg), Bg + (size_t)(lrow + 64) * HID + k0 + lseg);
        CP_COMMIT;
    }

    int r = lane & 15;
    uint32_t aB = smem_u32(Asm) + (uint32_t)((wm * 64 + r) * SPAD) * 2 + (lane & 16);
    uint32_t bB = smem_u32(Bsm) + (uint32_t)((wn * 32 + r) * SPAD) * 2 + (lane & 16);

    for (int i = 0; i < L; i++) {
        CP_WAIT2;
        __syncthreads();
        int pf = i + FSTAGES - 1;
        if (pf < L) {
            int k0 = pf * 32, st = pf & (FSTAGES - 1);
            cp_async16(smem_u32(Asm + st * STG_E + lrow * SPAD + lseg), Ag + (size_t)lrow * HID + k0 + lseg);
            cp_async16(smem_u32(Asm + st * STG_E + (lrow + 64) * SPAD + lseg), Ag + (size_t)(lrow + 64) * HID + k0 + lseg);
            cp_async16(smem_u32(Bsm + st * STG_E + lrow * SPAD + lseg), Bg + (size_t)lrow * HID + k0 + lseg);
            cp_async16(smem_u32(Bsm + st * STG_E + (lrow + 64) * SPAD + lseg), Bg + (size_t)(lrow + 64) * HID + k0 + lseg);
        }
        CP_COMMIT;
        int st = i & (FSTAGES - 1);
        uint32_t aS = aB + st * (STG_E * 2);
        uint32_t bS = bB + st * (STG_E * 2);
#pragma unroll
        for (int s = 0; s < 2; s++) {
            uint32_t a[4][4], bb[2][4];
#pragma unroll
            for (int mt = 0; mt < 4; mt++)
                ldsm4(a[mt], aS + mt * (16 * SPAD * 2) + s * 32);
#pragma unroll
            for (int ng = 0; ng < 2; ng++)
                ldsm4(bb[ng], bS + ng * (16 * SPAD * 2) + s * 32);
#pragma unroll
            for (int mt = 0; mt < 4; mt++)
#pragma unroll
                for (int nt = 0; nt < 4; nt++)
                    mma16816(d[mt][nt], a[mt], bb[nt >> 1][nt & 1], bb[nt >> 1][2 + (nt & 1)]);
        }
    }

    int g = lane >> 2, qq = lane & 3;
    const float* xb = x + (size_t)b * C * N + j0;
    float* ob = out + (size_t)b * C * N + j0;
#pragma unroll
    for (int mt = 0; mt < 4; mt++) {
        int o_r = o0 + wm * 64 + mt * 16 + g;
        float bo0 = bout[o_r], bo1 = bout[o_r + 8];
#pragma unroll
        for (int nt = 0; nt < 4; nt++) {
            int jc = wn * 32 + nt * 8 + qq * 2;
            float2 x0 = *(const float2*)(xb + (size_t)o_r * N + jc);
            float2 x1 = *(const float2*)(xb + (size_t)(o_r + 8) * N + jc);
            float2 v0, v1;
            v0.x = d[mt][nt][0] + bo0 + x0.x;
            v0.y = d[mt][nt][1] + bo0 + x0.y;
            v1.x = d[mt][nt][2] + bo1 + x1.x;
            v1.y = d[mt][nt][3] + bo1 + x1.y;
            *(float2*)(ob + (size_t)o_r * N + jc) = v0;
            *(float2*)(ob + (size_t)(o_r + 8) * N + jc) = v1;
        }
    }
}

// ---------------------------------------------------------------------------
extern "C" void kernel_launch(void* const* d_in, const int* in_sizes, int n_in,
                              void* d_out, int out_size) {
    const float* x = (const float*)d_in[0];
    const float* g = (const float*)d_in[1];
    const float* bln = (const float*)d_in[2];
    const float* wqkv = (const float*)d_in[3];
    const float* wout = (const float*)d_in[4];
    const float* bout = (const float*)d_in[5];
    float* out = (float*)d_out;

    cudaFuncSetAttribute(qkv_mma, cudaFuncAttributeMaxDynamicSharedMemorySize, QKV_DSM_B);
    cudaFuncSetAttribute(final_mma, cudaFuncAttributeMaxDynamicSharedMemorySize, FIN_DSM_B);

    prep_w<<<QKV_ROWS, 256>>>(wqkv, g, bln);
    transpose_x<<<dim3(N / 64, C / 64, BATCH), 256>>>(x);
    ln_finalize<<<BATCH * N / 256, 256>>>();
    qkv_mma<<<dim3(N / 128, QKV_ROWS / 128, BATCH), 256, QKV_DSM_B>>>();
    k_merge<<<BATCH * HID / 8, 256>>>();
    ctx_partial<<<dim3(NSEG, BATCH * HEADS), 256>>>();
    fold_w<<<dim3(HEADS, BATCH), 256>>>(wout);
    final_mma<<<dim3(N / 128, C / 128, BATCH), 256, FIN_DSM_B>>>(bout, x, out);
}